// round 8
// baseline (speedup 1.0000x reference)
#include <cuda_runtime.h>
#include <cuda_bf16.h>
#include <cstdint>
#include <stdint.h>
#include <math.h>

// ---------------- problem constants ----------------
#define N1   8192
#define N2   4096
#define TT   15
#define BS   4
#define E1C  131072
#define E2C  65536
#define KCH  12
#define G1C  64
#define G2C  32
#define NC   6

// ---------------- float scratch layout ----------------
#define T1_STRIDE (N1*64)
#define OFF_T1    0
#define OFF_Y1    (OFF_T1 + 3*T1_STRIDE)
#define T2_STRIDE (N2*256)
#define OFF_T2    (OFF_Y1 + N1*256)
#define OFF_Y2    (OFF_T2 + 3*T2_STRIDE)
#define OFF_NORM1 (OFF_Y2 + N2*128)
#define OFF_NORM2 (OFF_NORM1 + E1C)
#define OFF_DEG1  (OFF_NORM2 + E2C)
#define OFF_DEG2  (OFF_DEG1 + N1)
#define OFF_LOG   (OFF_DEG2 + N2)
#define OFF_FCP   (OFF_LOG + 64)
#define OFF_PART  (OFF_FCP + 256)
#define SCRATCH_F (OFF_PART + 4*N2*256)

__device__ float g_f[SCRATCH_F];

// bf16 split buffers for B^T only (A converted inline in the GEMM)
__device__ __nv_bfloat16 g_Bthi[(size_t)256 * N1]; // B^T: [256][8192]
__device__ __nv_bfloat16 g_Btlo[(size_t)256 * N1];

// ---------------- int scratch layout ----------------
#define IO_FLAG  0
#define IO_RP1   1
#define IO_CU1   (IO_RP1 + N1 + 1)
#define IO_EI1   (IO_CU1 + N1)
#define IO_SRC1  (IO_EI1 + E1C)
#define IO_DST1  (IO_SRC1 + E1C)
#define IO_RP2   (IO_DST1 + E1C)
#define IO_CU2   (IO_RP2 + N2 + 1)
#define IO_EI2   (IO_CU2 + N2)
#define IO_SRC2  (IO_EI2 + E2C)
#define IO_DST2  (IO_SRC2 + E2C)
#define SCRATCH_I (IO_DST2 + E2C)

__device__ int g_i[SCRATCH_I];

// ---------------- grid barrier state ----------------
__device__ unsigned int g_bc[2];
__device__ unsigned int g_bg[2];

#define CONV_CTAS 256

__device__ __forceinline__ void gridbar(int which, unsigned target) {
    if (threadIdx.x == 0) {
        __threadfence();
        unsigned o = atomicAdd(&g_bc[which], 1u);
        if (o == CONV_CTAS - 1u) {
            atomicExch(&g_bc[which], 0u);
            __threadfence();
            atomicAdd(&g_bg[which], 1u);
        } else {
            unsigned cur;
            do {
                asm volatile("ld.acquire.gpu.global.u32 %0, [%1];"
                             : "=r"(cur) : "l"(&g_bg[which]) : "memory");
                if (cur < target) __nanosleep(128);
            } while (cur < target);
        }
    }
    __syncthreads();
}

// ================= helpers =================

__device__ __forceinline__ uint32_t smem_u32(const void* p) {
    uint32_t a;
    asm("{ .reg .u64 t; cvta.to.shared.u64 t, %1; cvt.u32.u64 %0, t; }" : "=r"(a) : "l"(p));
    return a;
}

#define CP16(dst, src) \
    asm volatile("cp.async.cg.shared.global [%0], [%1], 16;" :: "r"(dst), "l"(src))
#define CP_COMMIT() asm volatile("cp.async.commit_group;" ::: "memory")
#define CP_WAIT1()  asm volatile("cp.async.wait_group 1;" ::: "memory")

#define LDS32(v, a) asm volatile("ld.shared.b32 %0, [%1];" : "=r"(v) : "r"(a))

#define MMA_BF16(c, a, b) \
    asm volatile("mma.sync.aligned.m16n8k16.row.col.f32.bf16.bf16.f32 " \
        "{%0,%1,%2,%3}, {%4,%5,%6,%7}, {%8,%9}, {%0,%1,%2,%3};" \
        : "+f"((c)[0]), "+f"((c)[1]), "+f"((c)[2]), "+f"((c)[3]) \
        : "r"((a)[0]), "r"((a)[1]), "r"((a)[2]), "r"((a)[3]), \
          "r"((b)[0]), "r"((b)[1]))

__device__ __forceinline__ void split_bf16(float v, unsigned short& h, unsigned short& l) {
    h = __bfloat16_as_ushort(__float2bfloat16(v));
    float r = v - __bfloat162float(__ushort_as_bfloat16(h));
    l = __bfloat16_as_ushort(__float2bfloat16(r));
}

// ================= preprocessing (merged) =================

__global__ void k_zero() {
    int i = blockIdx.x * blockDim.x + threadIdx.x;
    if (i == 0) {
        g_i[IO_FLAG] = 0;
        g_bc[0] = 0; g_bc[1] = 0;
        g_bg[0] = 0; g_bg[1] = 0;
    }
    if (i < N1) g_i[IO_CU1 + i] = 0;
    if (i < N2) g_i[IO_CU2 + i] = 0;
}

__global__ void k_detect(const long long* p) {
    int e = blockIdx.x * blockDim.x + threadIdx.x;
    if (e < E1C) {
        long long v = p[e];
        if (v < 0 || v >= (long long)N1) atomicOr(&g_i[IO_FLAG], 1);
    }
}

__global__ void k_decode2(const void* ei1, const void* ei2) {
    int e = blockIdx.x * blockDim.x + threadIdx.x;
    int is32 = g_i[IO_FLAG];
    const void* eiv; int E, srcOff, dstOff, le;
    if (e < E1C) { eiv = ei1; E = E1C; srcOff = IO_SRC1; dstOff = IO_DST1; le = e; }
    else if (e < E1C + E2C) { eiv = ei2; E = E2C; srcOff = IO_SRC2; dstOff = IO_DST2; le = e - E1C; }
    else return;
    int s, d;
    if (is32) {
        const int* p = (const int*)eiv;
        s = p[le]; d = p[E + le];
    } else {
        const long long* p = (const long long*)eiv;
        s = (int)p[le]; d = (int)p[E + le];
    }
    g_i[srcOff + le] = s;
    g_i[dstOff + le] = d;
}

__global__ void k_count2() {
    int e = blockIdx.x * blockDim.x + threadIdx.x;
    if (e < E1C) atomicAdd(&g_i[IO_CU1 + g_i[IO_DST1 + e]], 1);
    else if (e < E1C + E2C) atomicAdd(&g_i[IO_CU2 + g_i[IO_DST2 + e - E1C]], 1);
}

__global__ void k_scan2() {
    __shared__ int part[1024];
    int n, cntOff, rpOff;
    if (blockIdx.x == 0) { n = N1; cntOff = IO_CU1; rpOff = IO_RP1; }
    else                 { n = N2; cntOff = IO_CU2; rpOff = IO_RP2; }
    int t = threadIdx.x;
    int chunk = (n + 1023) >> 10;
    int base = t * chunk;
    int s = 0;
    for (int i = 0; i < chunk; i++) { int idx = base + i; if (idx < n) s += g_i[cntOff + idx]; }
    part[t] = s;
    __syncthreads();
    for (int off = 1; off < 1024; off <<= 1) {
        int v = (t >= off) ? part[t - off] : 0;
        __syncthreads();
        part[t] += v;
        __syncthreads();
    }
    int run = (t > 0) ? part[t - 1] : 0;
    for (int i = 0; i < chunk; i++) {
        int idx = base + i;
        if (idx < n) {
            int v = g_i[cntOff + idx];
            g_i[rpOff + idx] = run;
            g_i[cntOff + idx] = run;
            run += v;
        }
    }
    if (t == 1023) g_i[rpOff + n] = part[1023];
}

__global__ void k_fill2() {
    int e = blockIdx.x * blockDim.x + threadIdx.x;
    if (e < E1C) {
        int d = g_i[IO_DST1 + e];
        int p = atomicAdd(&g_i[IO_CU1 + d], 1);
        g_i[IO_EI1 + p] = e;
    } else if (e < E1C + E2C) {
        int le = e - E1C;
        int d = g_i[IO_DST2 + le];
        int p = atomicAdd(&g_i[IO_CU2 + d], 1);
        g_i[IO_EI2 + p] = le;
    }
}

__global__ void k_sortdeg(const float* w1, const float* w2) {
    int idx = blockIdx.x * blockDim.x + threadIdx.x;
    int rpOff, eidOff, degOff, node;
    const float* w;
    if (idx < N1) { node = idx; rpOff = IO_RP1; eidOff = IO_EI1; degOff = OFF_DEG1; w = w1; }
    else if (idx < N1 + N2) { node = idx - N1; rpOff = IO_RP2; eidOff = IO_EI2; degOff = OFF_DEG2; w = w2; }
    else return;
    int beg = g_i[rpOff + node], end = g_i[rpOff + node + 1];
    for (int i = beg + 1; i < end; i++) {
        int key = g_i[eidOff + i];
        int j = i - 1;
        while (j >= beg && g_i[eidOff + j] > key) {
            g_i[eidOff + j + 1] = g_i[eidOff + j];
            j--;
        }
        g_i[eidOff + j + 1] = key;
    }
    float s = 0.f;
    for (int i = beg; i < end; i++) s += w[g_i[eidOff + i]];
    g_f[degOff + node] = s;
}

__global__ void k_norm2(const float* w1, const float* w2) {
    int e = blockIdx.x * blockDim.x + threadIdx.x;
    int srcOff, dstOff, degOff, normOff, le;
    const float* w;
    if (e < E1C) { le = e; srcOff = IO_SRC1; dstOff = IO_DST1; degOff = OFF_DEG1; normOff = OFF_NORM1; w = w1; }
    else if (e < E1C + E2C) { le = e - E1C; srcOff = IO_SRC2; dstOff = IO_DST2; degOff = OFF_DEG2; normOff = OFF_NORM2; w = w2; }
    else return;
    float ds = g_f[degOff + g_i[srcOff + le]];
    float dd = g_f[degOff + g_i[dstOff + le]];
    float rs = (ds > 0.f) ? rsqrtf(ds) : 0.f;
    float rd = (dd > 0.f) ? rsqrtf(dd) : 0.f;
    g_f[normOff + le] = -w[le] * rs * rd;
}

// ================= persistent conv1 =================
// 256 CTAs x 256 threads; CTA owns 32 nodes (4 batches of 8, warp per node).
// y accumulated in registers; T_{k-2} kept in registers; grid barrier between steps.

__global__ void __launch_bounds__(256, 2) k_conv1(const float* __restrict__ x,
                                                  const float* __restrict__ W1,
                                                  const float* __restrict__ bias1) {
    __shared__ float sW[TT * G1C];
    __shared__ float sT[8 * 64];
    int tid = threadIdx.x, warp = tid >> 5, lane = tid & 31;
    int half = lane >> 4, c4 = lane & 15;
    int cta = blockIdx.x;
    int g = tid >> 2, b = tid & 3;
    float y[4][8];
    float4 t1[4], t2[4];

    for (int i = tid; i < TT * G1C; i += 256) sW[i] = W1[i];
    float bv = bias1[g];

    // step 0: xpose + T0 + ein0
#pragma unroll
    for (int batch = 0; batch < 4; batch++) {
        int node = cta * 32 + batch * 8 + warp;
        sT[warp * 64 + lane] = 0.f;
        sT[warp * 64 + 32 + lane] = 0.f;
        __syncwarp();
#pragma unroll
        for (int r = 0; r < 2; r++) {
            int idx = r * 32 + lane;
            if (idx < 60) {
                int bb = idx / 15, d = idx % 15;
                sT[warp * 64 + d * 4 + bb] = x[(size_t)bb * (N1 * TT) + node * TT + d];
            }
        }
        __syncwarp();
        if (half == 0) {
            float4 v = *(float4*)&sT[warp * 64 + c4 * 4];
            t1[batch] = v;
            ((float4*)(g_f + OFF_T1))[node * 16 + c4] = v;
        }
        __syncthreads();
#pragma unroll
        for (int ns = 0; ns < 8; ns++) {
            float s = 0.f;
#pragma unroll
            for (int d = 0; d < TT; d++) s = fmaf(sT[ns * 64 + d * 4 + b], sW[d * G1C + g], s);
            y[batch][ns] = s + bv;
        }
        __syncthreads();
    }
    gridbar(0, 1);

    const int bufs[3] = {OFF_T1, OFF_T1 + T1_STRIDE, OFF_T1 + 2 * T1_STRIDE};
    for (int k = 1; k < KCH; k++) {
        for (int i = tid; i < TT * G1C; i += 256) sW[i] = W1[k * TT * G1C + i];
        int inOff = bufs[(k - 1) % 3], outOff = bufs[k % 3];
#pragma unroll
        for (int batch = 0; batch < 4; batch++) {
            int node = cta * 32 + batch * 8 + warp;
            int beg = g_i[IO_RP1 + node], end = g_i[IO_RP1 + node + 1];
            const float4* in = (const float4*)(g_f + inOff);
            float4 acc = make_float4(0.f, 0.f, 0.f, 0.f);
            for (int i = beg + half; i < end; i += 2) {
                int e = g_i[IO_EI1 + i];
                float nm = g_f[OFF_NORM1 + e];
                int s = g_i[IO_SRC1 + e];
                float4 v = __ldcg(&in[s * 16 + c4]);
                acc.x = fmaf(nm, v.x, acc.x);
                acc.y = fmaf(nm, v.y, acc.y);
                acc.z = fmaf(nm, v.z, acc.z);
                acc.w = fmaf(nm, v.w, acc.w);
            }
            acc.x += __shfl_down_sync(0xffffffffu, acc.x, 16);
            acc.y += __shfl_down_sync(0xffffffffu, acc.y, 16);
            acc.z += __shfl_down_sync(0xffffffffu, acc.z, 16);
            acc.w += __shfl_down_sync(0xffffffffu, acc.w, 16);
            if (half == 0) {
                float4 r = acc;
                if (k >= 2) {
                    r.x = 2.f * r.x - t2[batch].x;
                    r.y = 2.f * r.y - t2[batch].y;
                    r.z = 2.f * r.z - t2[batch].z;
                    r.w = 2.f * r.w - t2[batch].w;
                }
                t2[batch] = t1[batch];
                t1[batch] = r;
                ((float4*)(g_f + outOff))[node * 16 + c4] = r;
                *(float4*)&sT[warp * 64 + c4 * 4] = r;
            }
            __syncthreads();
#pragma unroll
            for (int ns = 0; ns < 8; ns++) {
                float s = 0.f;
#pragma unroll
                for (int d = 0; d < TT; d++) s = fmaf(sT[ns * 64 + d * 4 + b], sW[d * G1C + g], s);
                y[batch][ns] += s;
            }
            __syncthreads();
        }
        if (k < KCH - 1) gridbar(0, (unsigned)(k + 1));
    }

    // write Y1 once
#pragma unroll
    for (int batch = 0; batch < 4; batch++) {
        int n0 = cta * 32 + batch * 8;
#pragma unroll
        for (int ns = 0; ns < 8; ns++)
            g_f[OFF_Y1 + (size_t)(n0 + ns) * 256 + tid] = y[batch][ns];
    }
}

// ================= persistent conv2 =================
// 256 CTAs x 256 threads; CTA owns 16 nodes (2 batches of 8, warp per node).

__global__ void __launch_bounds__(256, 2) k_conv2(const float* __restrict__ W2,
                                                  const float* __restrict__ bias2) {
    __shared__ float sW[G1C * G2C];
    __shared__ float sT[8 * 256];
    int tid = threadIdx.x, warp = tid >> 5, lane = tid & 31;
    int cta = blockIdx.x;
    int local = tid & 127, sub = tid >> 7;
    int g = local >> 2, b = local & 3;
    float y[2][4];
    float4 t1a[2], t1b[2], t2a[2], t2b[2];

    for (int i = tid; i < G1C * G2C; i += 256) sW[i] = W2[i];
    float bv = bias2[g];

    // step 0: reduce GEMM partials -> T0 + ein0
#pragma unroll
    for (int batch = 0; batch < 2; batch++) {
        int node = cta * 16 + batch * 8 + warp;
        const float4* p0 = (const float4*)(g_f + OFF_PART) + (size_t)node * 64;
        const float4* p1 = (const float4*)(g_f + OFF_PART + (N2 * 256)) + (size_t)node * 64;
        const float4* p2 = (const float4*)(g_f + OFF_PART + 2 * (N2 * 256)) + (size_t)node * 64;
        const float4* p3 = (const float4*)(g_f + OFF_PART + 3 * (N2 * 256)) + (size_t)node * 64;
        float4 a0 = p0[lane], b0 = p1[lane], c0 = p2[lane], d0 = p3[lane];
        float4 a1 = p0[lane + 32], b1 = p1[lane + 32], c1 = p2[lane + 32], d1 = p3[lane + 32];
        float4 v0 = make_float4(a0.x + b0.x + c0.x + d0.x, a0.y + b0.y + c0.y + d0.y,
                                a0.z + b0.z + c0.z + d0.z, a0.w + b0.w + c0.w + d0.w);
        float4 v1 = make_float4(a1.x + b1.x + c1.x + d1.x, a1.y + b1.y + c1.y + d1.y,
                                a1.z + b1.z + c1.z + d1.z, a1.w + b1.w + c1.w + d1.w);
        t1a[batch] = v0; t1b[batch] = v1;
        float4* o = (float4*)(g_f + OFF_T2) + (size_t)node * 64;
        o[lane] = v0; o[lane + 32] = v1;
        *(float4*)&sT[warp * 256 + lane * 4] = v0;
        *(float4*)&sT[warp * 256 + 128 + lane * 4] = v1;
        __syncthreads();
#pragma unroll
        for (int pass = 0; pass < 4; pass++) {
            int ns = pass * 2 + sub;
            float s = 0.f;
#pragma unroll
            for (int d = 0; d < G1C; d++) s = fmaf(sT[ns * 256 + d * 4 + b], sW[d * G2C + g], s);
            y[batch][pass] = s + bv;
        }
        __syncthreads();
    }
    gridbar(1, 1);

    const int bufs[3] = {OFF_T2, OFF_T2 + T2_STRIDE, OFF_T2 + 2 * T2_STRIDE};
    for (int k = 1; k < KCH; k++) {
        for (int i = tid; i < G1C * G2C; i += 256) sW[i] = W2[k * G1C * G2C + i];
        int inOff = bufs[(k - 1) % 3], outOff = bufs[k % 3];
#pragma unroll
        for (int batch = 0; batch < 2; batch++) {
            int node = cta * 16 + batch * 8 + warp;
            int beg = g_i[IO_RP2 + node], end = g_i[IO_RP2 + node + 1];
            const float4* in = (const float4*)(g_f + inOff);
            float4 a0 = make_float4(0.f, 0.f, 0.f, 0.f);
            float4 a1 = a0;
            for (int i = beg; i < end; i++) {
                int e = g_i[IO_EI2 + i];
                float nm = g_f[OFF_NORM2 + e];
                int s = g_i[IO_SRC2 + e];
                const float4* row = in + (size_t)s * 64;
                float4 v0 = __ldcg(&row[lane]);
                float4 v1 = __ldcg(&row[lane + 32]);
                a0.x = fmaf(nm, v0.x, a0.x); a0.y = fmaf(nm, v0.y, a0.y);
                a0.z = fmaf(nm, v0.z, a0.z); a0.w = fmaf(nm, v0.w, a0.w);
                a1.x = fmaf(nm, v1.x, a1.x); a1.y = fmaf(nm, v1.y, a1.y);
                a1.z = fmaf(nm, v1.z, a1.z); a1.w = fmaf(nm, v1.w, a1.w);
            }
            if (k >= 2) {
                a0.x = 2.f * a0.x - t2a[batch].x; a0.y = 2.f * a0.y - t2a[batch].y;
                a0.z = 2.f * a0.z - t2a[batch].z; a0.w = 2.f * a0.w - t2a[batch].w;
                a1.x = 2.f * a1.x - t2b[batch].x; a1.y = 2.f * a1.y - t2b[batch].y;
                a1.z = 2.f * a1.z - t2b[batch].z; a1.w = 2.f * a1.w - t2b[batch].w;
            }
            t2a[batch] = t1a[batch]; t2b[batch] = t1b[batch];
            t1a[batch] = a0; t1b[batch] = a1;
            float4* o = (float4*)(g_f + outOff) + (size_t)node * 64;
            o[lane] = a0; o[lane + 32] = a1;
            *(float4*)&sT[warp * 256 + lane * 4] = a0;
            *(float4*)&sT[warp * 256 + 128 + lane * 4] = a1;
            __syncthreads();
#pragma unroll
            for (int pass = 0; pass < 4; pass++) {
                int ns = pass * 2 + sub;
                float s = 0.f;
#pragma unroll
                for (int d = 0; d < G1C; d++) s = fmaf(sT[ns * 256 + d * 4 + b], sW[d * G2C + g], s);
                y[batch][pass] += s;
            }
            __syncthreads();
        }
        if (k < KCH - 1) gridbar(1, (unsigned)(k + 1));
    }

    // write Y2 once
#pragma unroll
    for (int batch = 0; batch < 2; batch++) {
        int n0 = cta * 16 + batch * 8;
#pragma unroll
        for (int pass = 0; pass < 4; pass++) {
            int ns = pass * 2 + sub;
            g_f[OFF_Y2 + (size_t)(n0 + ns) * 128 + local] = y[batch][pass];
        }
    }
}

// ================= B^T split conversion (relu fused) =================

__global__ void k_convBT() {
    __shared__ float s[64][65];
    int kt = blockIdx.x >> 2, nt = blockIdx.x & 3;
    int k0 = kt * 64, n0 = nt * 64;
    int t = threadIdx.x;
    {
        int r = t >> 4, c4 = t & 15;
#pragma unroll
        for (int i = 0; i < 4; i++) {
            int row = r + i * 16;
            float4 v = *(const float4*)&g_f[OFF_Y1 + (size_t)(k0 + row) * 256 + n0 + c4 * 4];
            s[row][c4 * 4 + 0] = fmaxf(v.x, 0.f);
            s[row][c4 * 4 + 1] = fmaxf(v.y, 0.f);
            s[row][c4 * 4 + 2] = fmaxf(v.z, 0.f);
            s[row][c4 * 4 + 3] = fmaxf(v.w, 0.f);
        }
    }
    __syncthreads();
    int n = t >> 2, kc = t & 3;
    unsigned short h[16], l[16];
#pragma unroll
    for (int e = 0; e < 16; e++) {
        split_bf16(s[kc * 16 + e][n], h[e], l[e]);
    }
    size_t ob = (size_t)(n0 + n) * N1 + k0 + kc * 16;
    uint4* dh = (uint4*)(g_Bthi + ob);
    uint4* dl = (uint4*)(g_Btlo + ob);
#pragma unroll
    for (int half = 0; half < 2; half++) {
        int e0 = half * 8;
        dh[half] = make_uint4((uint32_t)h[e0] | ((uint32_t)h[e0+1] << 16),
                              (uint32_t)h[e0+2] | ((uint32_t)h[e0+3] << 16),
                              (uint32_t)h[e0+4] | ((uint32_t)h[e0+5] << 16),
                              (uint32_t)h[e0+6] | ((uint32_t)h[e0+7] << 16));
        dl[half] = make_uint4((uint32_t)l[e0] | ((uint32_t)l[e0+1] << 16),
                              (uint32_t)l[e0+2] | ((uint32_t)l[e0+3] << 16),
                              (uint32_t)l[e0+4] | ((uint32_t)l[e0+5] << 16),
                              (uint32_t)l[e0+6] | ((uint32_t)l[e0+7] << 16));
    }
}

// ================= mma.sync split-bf16 GEMM (A converted inline) =================

#define SA_H 0
#define SA_L 10240
#define SB_H 20480
#define SB_L 40960
#define GSTAGE 61440
#define GSM_TOTAL (2 * GSTAGE)
#define NKCHUNK 64   // 2048 / 32

__global__ void __launch_bounds__(512, 1) k_gemm_mma(const float* __restrict__ Agl) {
    extern __shared__ char smem[];
    uint32_t sb = smem_u32(smem);
    int tid = threadIdx.x, lane = tid & 31, wid = tid >> 5;
    int mt = blockIdx.x, ks = blockIdx.y;
    int bm = mt * 128;
    int kbase = ks * 2048;

    const __nv_bfloat16* Bh = g_Bthi;
    const __nv_bfloat16* Bl = g_Btlo;

    int arow = tid >> 2, ach = tid & 3;
    int brow = tid >> 1, bch = tid & 1;
    const float* Arow = Agl + (size_t)(bm + arow) * N1 + kbase + ach * 8;

#define LOADB(kc, st) do { \
        int kb_ = kbase + (kc) * 32 + bch * 16; \
        uint32_t db_ = sb + (st) * GSTAGE + brow * 80 + bch * 32; \
        CP16(db_ + SB_H,      Bh + (size_t)brow * N1 + kb_); \
        CP16(db_ + SB_H + 16, Bh + (size_t)brow * N1 + kb_ + 8); \
        CP16(db_ + SB_L,      Bl + (size_t)brow * N1 + kb_); \
        CP16(db_ + SB_L + 16, Bl + (size_t)brow * N1 + kb_ + 8); \
    } while (0)

#define STS_A(v0, v1, st) do { \
        unsigned short h_[8], l_[8]; \
        split_bf16((v0).x, h_[0], l_[0]); split_bf16((v0).y, h_[1], l_[1]); \
        split_bf16((v0).z, h_[2], l_[2]); split_bf16((v0).w, h_[3], l_[3]); \
        split_bf16((v1).x, h_[4], l_[4]); split_bf16((v1).y, h_[5], l_[5]); \
        split_bf16((v1).z, h_[6], l_[6]); split_bf16((v1).w, h_[7], l_[7]); \
        uint32_t da_ = sb + (st) * GSTAGE + arow * 80 + ach * 16; \
        *(uint4*)(smem + (da_ - sb) + SA_H) = make_uint4( \
            (uint32_t)h_[0] | ((uint32_t)h_[1] << 16), (uint32_t)h_[2] | ((uint32_t)h_[3] << 16), \
            (uint32_t)h_[4] | ((uint32_t)h_[5] << 16), (uint32_t)h_[6] | ((uint32_t)h_[7] << 16)); \
        *(uint4*)(smem + (da_ - sb) + SA_L) = make_uint4( \
            (uint32_t)l_[0] | ((uint32_t)l_[1] << 16), (uint32_t)l_[2] | ((uint32_t)l_[3] << 16), \
            (uint32_t)l_[4] | ((uint32_t)l_[5] << 16), (uint32_t)l_[6] | ((uint32_t)l_[7] << 16)); \
    } while (0)

    {
        float4 a0 = *(const float4*)(Arow + 0 * 32);
        float4 a1 = *(const float4*)(Arow + 0 * 32 + 4);
        STS_A(a0, a1, 0);
        float4 b0 = *(const float4*)(Arow + 1 * 32);
        float4 b1 = *(const float4*)(Arow + 1 * 32 + 4);
        STS_A(b0, b1, 1);
    }
    LOADB(0, 0); CP_COMMIT();
    LOADB(1, 1); CP_COMMIT();

    int mw = wid & 3, nw = wid >> 2;
    float acc[2][8][4];
#pragma unroll
    for (int f = 0; f < 2; f++)
#pragma unroll
        for (int g = 0; g < 8; g++)
#pragma unroll
            for (int q = 0; q < 4; q++) acc[f][g][q] = 0.f;

    int qrow = lane >> 2, qk = (lane & 3) * 2;

    for (int kc = 0; kc < NKCHUNK; kc++) {
        int st = kc & 1;
        CP_WAIT1();
        __syncthreads();
        float4 pa0, pa1;
        bool pre = (kc + 2 < NKCHUNK);
        if (pre) {
            pa0 = *(const float4*)(Arow + (kc + 2) * 32);
            pa1 = *(const float4*)(Arow + (kc + 2) * 32 + 4);
        }
        uint32_t base = sb + st * GSTAGE;
#pragma unroll
        for (int kk = 0; kk < 32; kk += 16) {
            uint32_t ah[2][4], al[2][4];
#pragma unroll
            for (int f = 0; f < 2; f++) {
                uint32_t a0 = base + (mw * 32 + f * 16 + qrow) * 80 + (qk + kk) * 2;
                LDS32(ah[f][0], a0 + SA_H);
                LDS32(ah[f][1], a0 + SA_H + 8 * 80);
                LDS32(ah[f][2], a0 + SA_H + 16);
                LDS32(ah[f][3], a0 + SA_H + 8 * 80 + 16);
                LDS32(al[f][0], a0 + SA_L);
                LDS32(al[f][1], a0 + SA_L + 8 * 80);
                LDS32(al[f][2], a0 + SA_L + 16);
                LDS32(al[f][3], a0 + SA_L + 8 * 80 + 16);
            }
#pragma unroll
            for (int g = 0; g < 8; g++) {
                uint32_t bh[2], bl[2];
                uint32_t b0 = base + (nw * 64 + g * 8 + qrow) * 80 + (qk + kk) * 2;
                LDS32(bh[0], b0 + SB_H);
                LDS32(bh[1], b0 + SB_H + 16);
                LDS32(bl[0], b0 + SB_L);
                LDS32(bl[1], b0 + SB_L + 16);
#pragma unroll
                for (int f = 0; f < 2; f++) {
                    MMA_BF16(acc[f][g], ah[f], bh);
                    MMA_BF16(acc[f][g], ah[f], bl);
                    MMA_BF16(acc[f][g], al[f], bh);
                }
            }
        }
        __syncthreads();
        if (pre) {
            STS_A(pa0, pa1, st);
            LOADB(kc + 2, st);
        }
        CP_COMMIT();
    }
#undef LOADB
#undef STS_A

    float* part = g_f + OFF_PART + (size_t)ks * (N2 * 256);
#pragma unroll
    for (int f = 0; f < 2; f++) {
        int row = bm + mw * 32 + f * 16 + qrow;
#pragma unroll
        for (int g = 0; g < 8; g++) {
            int col = nw * 64 + g * 8 + (lane & 3) * 2;
            *(float2*)&part[(size_t)row * 256 + col] = make_float2(acc[f][g][0], acc[f][g][1]);
            *(float2*)&part[(size_t)(row + 8) * 256 + col] = make_float2(acc[f][g][2], acc[f][g][3]);
        }
    }
}

// ================= classifier =================

__global__ void k_fc(const float* __restrict__ fcw) {
    int blk = blockIdx.x;
    int q = blk / 48, rem = blk % 48, c = rem / 8, ks = rem % 8;
    __shared__ float red[256];
    const float4* y = (const float4*)(g_f + OFF_Y2 + (size_t)q * 131072 + ks * 16384);
    const float4* w = (const float4*)(fcw + (size_t)c * 131072 + ks * 16384);
    float s = 0.f;
#pragma unroll
    for (int it = 0; it < 16; it++) {
        int j = it * 256 + threadIdx.x;
        float4 a = y[j], b = w[j];
        s = fmaf(a.x, b.x, s); s = fmaf(a.y, b.y, s);
        s = fmaf(a.z, b.z, s); s = fmaf(a.w, b.w, s);
    }
    red[threadIdx.x] = s;
    __syncthreads();
    for (int o = 128; o > 0; o >>= 1) {
        if (threadIdx.x < o) red[threadIdx.x] += red[threadIdx.x + o];
        __syncthreads();
    }
    if (threadIdx.x == 0) g_f[OFF_FCP + blk] = red[0];
}

__global__ void k_lsm(const float* __restrict__ fcb, float* out) {
    __shared__ float logit[24];
    int t = threadIdx.x;
    if (t < 24) {
        int q = t / 6, c = t % 6;
        float s = fcb[c];
#pragma unroll
        for (int i = 0; i < 8; i++) s += g_f[OFF_FCP + q * 48 + c * 8 + i];
        logit[t] = s;
    }
    __syncwarp();
    if (t < 4) {
        float m = -1e30f;
        for (int c = 0; c < 6; c++) m = fmaxf(m, logit[t * 6 + c]);
        float se = 0.f;
        for (int c = 0; c < 6; c++) se += expf(logit[t * 6 + c] - m);
        float l = logf(se);
        for (int c = 0; c < 6; c++) out[t * 6 + c] = logit[t * 6 + c] - m - l;
    }
}

// ================= host =================

extern "C" void kernel_launch(void* const* d_in, const int* in_sizes, int n_in,
                              void* d_out, int out_size) {
    const float*     x    = (const float*)d_in[0];
    const void*      ei1  = d_in[1];
    const float*     w1e  = (const float*)d_in[2];
    const void*      ei2  = d_in[3];
    const float*     w2e  = (const float*)d_in[4];
    const float*     bmap = (const float*)d_in[5];
    const float*     W1   = (const float*)d_in[6];
    const float*     bias1= (const float*)d_in[7];
    const float*     W2   = (const float*)d_in[8];
    const float*     bias2= (const float*)d_in[9];
    const float*     fcw  = (const float*)d_in[10];
    const float*     fcb  = (const float*)d_in[11];
    float*           out  = (float*)d_out;
    (void)in_sizes; (void)n_in; (void)out_size;

    cudaFuncSetAttribute(k_gemm_mma, cudaFuncAttributeMaxDynamicSharedMemorySize, GSM_TOTAL);

    // --- preprocessing (8 launches) ---
    k_zero<<<(N1 + 255) / 256, 256>>>();
    k_detect<<<(E1C + 255) / 256, 256>>>((const long long*)ei1);
    k_decode2<<<(E1C + E2C + 255) / 256, 256>>>(ei1, ei2);
    k_count2<<<(E1C + E2C + 255) / 256, 256>>>();
    k_scan2<<<2, 1024>>>();
    k_fill2<<<(E1C + E2C + 255) / 256, 256>>>();
    k_sortdeg<<<(N1 + N2 + 127) / 128, 128>>>(w1e, w2e);
    k_norm2<<<(E1C + E2C + 255) / 256, 256>>>(w1e, w2e);

    // --- conv1: ONE persistent kernel (xpose + 12 Chebyshev terms) ---
    k_conv1<<<CONV_CTAS, 256>>>(x, W1, bias1);

    // --- split-bf16 mma GEMM (A converted inline; relu fused into convBT) ---
    k_convBT<<<512, 256>>>();
    dim3 gg(32, 4);
    k_gemm_mma<<<gg, 512, GSM_TOTAL>>>(bmap);

    // --- conv2: ONE persistent kernel (partial reduce + 12 Chebyshev terms) ---
    k_conv2<<<CONV_CTAS, 256>>>(W2, bias2);

    // --- fc + log_softmax ---
    k_fc<<<192, 256>>>(fcw);
    k_lsm<<<1, 32>>>(fcb, out);
}

// round 9
// speedup vs baseline: 1.0185x; 1.0185x over previous
#include <cuda_runtime.h>
#include <cuda_bf16.h>
#include <cstdint>
#include <stdint.h>
#include <math.h>

// ---------------- problem constants ----------------
#define N1   8192
#define N2   4096
#define TT   15
#define BS   4
#define E1C  131072
#define E2C  65536
#define KCH  12
#define G1C  64
#define G2C  32
#define NC   6

// ---------------- float scratch layout ----------------
#define T1_STRIDE (N1*64)
#define OFF_T1    0
#define OFF_Y1    (OFF_T1 + 3*T1_STRIDE)
#define T2_STRIDE (N2*256)
#define OFF_T2    (OFF_Y1 + N1*256)
#define OFF_Y2    (OFF_T2 + 3*T2_STRIDE)
#define OFF_NORM1 (OFF_Y2 + N2*128)
#define OFF_NORM2 (OFF_NORM1 + E1C)
#define OFF_DEG1  (OFF_NORM2 + E2C)
#define OFF_DEG2  (OFF_DEG1 + N1)
#define OFF_LOG   (OFF_DEG2 + N2)
#define OFF_FCP   (OFF_LOG + 64)
#define OFF_PART  (OFF_FCP + 256)
#define SCRATCH_F (OFF_PART + 4*N2*256)

__device__ float g_f[SCRATCH_F];

// bf16 split buffers for B^T only (A converted inline in the GEMM)
__device__ __nv_bfloat16 g_Bthi[(size_t)256 * N1]; // B^T: [256][8192]
__device__ __nv_bfloat16 g_Btlo[(size_t)256 * N1];

// packed CSR edge data: (norm, src-as-float-bits) in CSR position order
__device__ float2 g_pk1[E1C];
__device__ float2 g_pk2[E2C];

// ---------------- int scratch layout ----------------
#define IO_FLAG  0
#define IO_RP1   1
#define IO_CU1   (IO_RP1 + N1 + 1)
#define IO_EI1   (IO_CU1 + N1)
#define IO_SRC1  (IO_EI1 + E1C)
#define IO_DST1  (IO_SRC1 + E1C)
#define IO_RP2   (IO_DST1 + E1C)
#define IO_CU2   (IO_RP2 + N2 + 1)
#define IO_EI2   (IO_CU2 + N2)
#define IO_SRC2  (IO_EI2 + E2C)
#define IO_DST2  (IO_SRC2 + E2C)
#define SCRATCH_I (IO_DST2 + E2C)

__device__ int g_i[SCRATCH_I];

// ================= helpers =================

__device__ __forceinline__ uint32_t smem_u32(const void* p) {
    uint32_t a;
    asm("{ .reg .u64 t; cvta.to.shared.u64 t, %1; cvt.u32.u64 %0, t; }" : "=r"(a) : "l"(p));
    return a;
}

#define CP16(dst, src) \
    asm volatile("cp.async.cg.shared.global [%0], [%1], 16;" :: "r"(dst), "l"(src))
#define CP_COMMIT() asm volatile("cp.async.commit_group;" ::: "memory")
#define CP_WAIT1()  asm volatile("cp.async.wait_group 1;" ::: "memory")

#define LDS32(v, a) asm volatile("ld.shared.b32 %0, [%1];" : "=r"(v) : "r"(a))

#define MMA_BF16(c, a, b) \
    asm volatile("mma.sync.aligned.m16n8k16.row.col.f32.bf16.bf16.f32 " \
        "{%0,%1,%2,%3}, {%4,%5,%6,%7}, {%8,%9}, {%0,%1,%2,%3};" \
        : "+f"((c)[0]), "+f"((c)[1]), "+f"((c)[2]), "+f"((c)[3]) \
        : "r"((a)[0]), "r"((a)[1]), "r"((a)[2]), "r"((a)[3]), \
          "r"((b)[0]), "r"((b)[1]))

#define FMA4(acc, nm, v) do { \
    (acc).x = fmaf((nm), (v).x, (acc).x); \
    (acc).y = fmaf((nm), (v).y, (acc).y); \
    (acc).z = fmaf((nm), (v).z, (acc).z); \
    (acc).w = fmaf((nm), (v).w, (acc).w); } while (0)

__device__ __forceinline__ void split_bf16(float v, unsigned short& h, unsigned short& l) {
    h = __bfloat16_as_ushort(__float2bfloat16(v));
    float r = v - __bfloat162float(__ushort_as_bfloat16(h));
    l = __bfloat16_as_ushort(__float2bfloat16(r));
}

// ================= preprocessing (merged) =================

__global__ void k_zero() {
    int i = blockIdx.x * blockDim.x + threadIdx.x;
    if (i == 0) g_i[IO_FLAG] = 0;
    if (i < N1) g_i[IO_CU1 + i] = 0;
    if (i < N2) g_i[IO_CU2 + i] = 0;
}

__global__ void k_detect(const long long* p) {
    int e = blockIdx.x * blockDim.x + threadIdx.x;
    if (e < E1C) {
        long long v = p[e];
        if (v < 0 || v >= (long long)N1) atomicOr(&g_i[IO_FLAG], 1);
    }
}

__global__ void k_decode2(const void* ei1, const void* ei2) {
    int e = blockIdx.x * blockDim.x + threadIdx.x;
    int is32 = g_i[IO_FLAG];
    const void* eiv; int E, srcOff, dstOff, le;
    if (e < E1C) { eiv = ei1; E = E1C; srcOff = IO_SRC1; dstOff = IO_DST1; le = e; }
    else if (e < E1C + E2C) { eiv = ei2; E = E2C; srcOff = IO_SRC2; dstOff = IO_DST2; le = e - E1C; }
    else return;
    int s, d;
    if (is32) {
        const int* p = (const int*)eiv;
        s = p[le]; d = p[E + le];
    } else {
        const long long* p = (const long long*)eiv;
        s = (int)p[le]; d = (int)p[E + le];
    }
    g_i[srcOff + le] = s;
    g_i[dstOff + le] = d;
}

__global__ void k_count2() {
    int e = blockIdx.x * blockDim.x + threadIdx.x;
    if (e < E1C) atomicAdd(&g_i[IO_CU1 + g_i[IO_DST1 + e]], 1);
    else if (e < E1C + E2C) atomicAdd(&g_i[IO_CU2 + g_i[IO_DST2 + e - E1C]], 1);
}

__global__ void k_scan2() {
    __shared__ int part[1024];
    int n, cntOff, rpOff;
    if (blockIdx.x == 0) { n = N1; cntOff = IO_CU1; rpOff = IO_RP1; }
    else                 { n = N2; cntOff = IO_CU2; rpOff = IO_RP2; }
    int t = threadIdx.x;
    int chunk = (n + 1023) >> 10;
    int base = t * chunk;
    int s = 0;
    for (int i = 0; i < chunk; i++) { int idx = base + i; if (idx < n) s += g_i[cntOff + idx]; }
    part[t] = s;
    __syncthreads();
    for (int off = 1; off < 1024; off <<= 1) {
        int v = (t >= off) ? part[t - off] : 0;
        __syncthreads();
        part[t] += v;
        __syncthreads();
    }
    int run = (t > 0) ? part[t - 1] : 0;
    for (int i = 0; i < chunk; i++) {
        int idx = base + i;
        if (idx < n) {
            int v = g_i[cntOff + idx];
            g_i[rpOff + idx] = run;
            g_i[cntOff + idx] = run;
            run += v;
        }
    }
    if (t == 1023) g_i[rpOff + n] = part[1023];
}

__global__ void k_fill2() {
    int e = blockIdx.x * blockDim.x + threadIdx.x;
    if (e < E1C) {
        int d = g_i[IO_DST1 + e];
        int p = atomicAdd(&g_i[IO_CU1 + d], 1);
        g_i[IO_EI1 + p] = e;
    } else if (e < E1C + E2C) {
        int le = e - E1C;
        int d = g_i[IO_DST2 + le];
        int p = atomicAdd(&g_i[IO_CU2 + d], 1);
        g_i[IO_EI2 + p] = le;
    }
}

__global__ void k_sortdeg(const float* w1, const float* w2) {
    int idx = blockIdx.x * blockDim.x + threadIdx.x;
    int rpOff, eidOff, degOff, node;
    const float* w;
    if (idx < N1) { node = idx; rpOff = IO_RP1; eidOff = IO_EI1; degOff = OFF_DEG1; w = w1; }
    else if (idx < N1 + N2) { node = idx - N1; rpOff = IO_RP2; eidOff = IO_EI2; degOff = OFF_DEG2; w = w2; }
    else return;
    int beg = g_i[rpOff + node], end = g_i[rpOff + node + 1];
    for (int i = beg + 1; i < end; i++) {
        int key = g_i[eidOff + i];
        int j = i - 1;
        while (j >= beg && g_i[eidOff + j] > key) {
            g_i[eidOff + j + 1] = g_i[eidOff + j];
            j--;
        }
        g_i[eidOff + j + 1] = key;
    }
    float s = 0.f;
    for (int i = beg; i < end; i++) s += w[g_i[eidOff + i]];
    g_f[degOff + node] = s;
}

__global__ void k_norm2(const float* w1, const float* w2) {
    int e = blockIdx.x * blockDim.x + threadIdx.x;
    int srcOff, dstOff, degOff, normOff, le;
    const float* w;
    if (e < E1C) { le = e; srcOff = IO_SRC1; dstOff = IO_DST1; degOff = OFF_DEG1; normOff = OFF_NORM1; w = w1; }
    else if (e < E1C + E2C) { le = e - E1C; srcOff = IO_SRC2; dstOff = IO_DST2; degOff = OFF_DEG2; normOff = OFF_NORM2; w = w2; }
    else return;
    float ds = g_f[degOff + g_i[srcOff + le]];
    float dd = g_f[degOff + g_i[dstOff + le]];
    float rs = (ds > 0.f) ? rsqrtf(ds) : 0.f;
    float rd = (dd > 0.f) ? rsqrtf(dd) : 0.f;
    g_f[normOff + le] = -w[le] * rs * rd;
}

// pack (norm, src) in CSR position order -> one 8B load per edge in prop loops
__global__ void k_pack() {
    int p = blockIdx.x * blockDim.x + threadIdx.x;
    if (p < E1C) {
        int e = g_i[IO_EI1 + p];
        g_pk1[p] = make_float2(g_f[OFF_NORM1 + e], __int_as_float(g_i[IO_SRC1 + e]));
    } else if (p < E1C + E2C) {
        int lp = p - E1C;
        int e = g_i[IO_EI2 + lp];
        g_pk2[lp] = make_float2(g_f[OFF_NORM2 + e], __int_as_float(g_i[IO_SRC2 + e]));
    }
}

// ================= conv1: fused kernels =================

__global__ void k_xpose_ein0(const float* __restrict__ x, const float* __restrict__ W1,
                             const float* __restrict__ bias1) {
    __shared__ float sW[TT * G1C];
    __shared__ float sT[8 * 64];
    int tid = threadIdx.x;
    int n0 = blockIdx.x * 8;
    for (int i = tid; i < TT * G1C; i += 256) sW[i] = W1[i];
#pragma unroll
    for (int it = 0; it < 2; it++) {
        int i = it * 256 + tid;
        int ns = i >> 6, j = i & 63;
        int d = j >> 2, b = j & 3;
        float v = (d < TT) ? x[(size_t)b * (N1 * TT) + (n0 + ns) * TT + d] : 0.f;
        sT[i] = v;
        g_f[OFF_T1 + (n0 + ns) * 64 + j] = v;
    }
    __syncthreads();
    int g = tid >> 2, b = tid & 3;
    float bv = bias1[g];
#pragma unroll
    for (int ns = 0; ns < 8; ns++) {
        float s = 0.f;
#pragma unroll
        for (int d = 0; d < TT; d++) s = fmaf(sT[ns * 64 + d * 4 + b], sW[d * G1C + g], s);
        g_f[OFF_Y1 + (n0 + ns) * 256 + tid] = s + bv;
    }
}

// fused prop + ein for conv1 step k: grid N1/8, 256 threads (8 warps = 8 nodes)
// packed CSR + 4-deep MLP batching in the gather loop
__global__ void k_step1(int inOff, int outOff, int prevOff, int dbl,
                        const float* __restrict__ W1, int k) {
    __shared__ float sW[TT * G1C];
    __shared__ float sT[8 * 64];
    int tid = threadIdx.x;
    for (int i = tid; i < TT * G1C; i += 256) sW[i] = W1[k * TT * G1C + i];
    int warp = tid >> 5, lane = tid & 31;
    int node = blockIdx.x * 8 + warp;
    int half = lane >> 4, c4 = lane & 15;
    int beg = g_i[IO_RP1 + node], end = g_i[IO_RP1 + node + 1];
    const float4* in = (const float4*)(g_f + inOff);
    float4 acc = make_float4(0.f, 0.f, 0.f, 0.f);
    for (int i = beg + half; i < end; i += 8) {
        float2 p0 = g_pk1[i];
        float2 p1 = (i + 2 < end) ? g_pk1[i + 2] : make_float2(0.f, __int_as_float(0));
        float2 p2 = (i + 4 < end) ? g_pk1[i + 4] : make_float2(0.f, __int_as_float(0));
        float2 p3 = (i + 6 < end) ? g_pk1[i + 6] : make_float2(0.f, __int_as_float(0));
        float4 v0 = in[__float_as_int(p0.y) * 16 + c4];
        float4 v1 = in[__float_as_int(p1.y) * 16 + c4];
        float4 v2 = in[__float_as_int(p2.y) * 16 + c4];
        float4 v3 = in[__float_as_int(p3.y) * 16 + c4];
        FMA4(acc, p0.x, v0);
        FMA4(acc, p1.x, v1);
        FMA4(acc, p2.x, v2);
        FMA4(acc, p3.x, v3);
    }
    acc.x += __shfl_down_sync(0xffffffffu, acc.x, 16);
    acc.y += __shfl_down_sync(0xffffffffu, acc.y, 16);
    acc.z += __shfl_down_sync(0xffffffffu, acc.z, 16);
    acc.w += __shfl_down_sync(0xffffffffu, acc.w, 16);
    if (half == 0) {
        float4 r = acc;
        if (dbl) {
            float4 p = ((const float4*)(g_f + prevOff))[node * 16 + c4];
            r.x = 2.f * r.x - p.x;
            r.y = 2.f * r.y - p.y;
            r.z = 2.f * r.z - p.z;
            r.w = 2.f * r.w - p.w;
        }
        ((float4*)(g_f + outOff))[node * 16 + c4] = r;
        *(float4*)&sT[warp * 64 + c4 * 4] = r;
    }
    __syncthreads();
    int g = tid >> 2, b = tid & 3;
    int n0 = blockIdx.x * 8;
#pragma unroll
    for (int ns = 0; ns < 8; ns++) {
        float s = 0.f;
#pragma unroll
        for (int d = 0; d < TT; d++) s = fmaf(sT[ns * 64 + d * 4 + b], sW[d * G1C + g], s);
        g_f[OFF_Y1 + (n0 + ns) * 256 + tid] += s;
    }
}

// ================= conv2: fused kernels =================

__global__ void k_red_ein0(const float* __restrict__ W2, const float* __restrict__ bias2) {
    __shared__ float sW[G1C * G2C];
    __shared__ float sT[8 * 256];
    int tid = threadIdx.x;
    int n0 = blockIdx.x * 8;
    for (int i = tid; i < G1C * G2C; i += 256) sW[i] = W2[i];
#pragma unroll
    for (int ns = 0; ns < 8; ns++) {
        size_t gi = (size_t)(n0 + ns) * 256 + tid;
        float v = g_f[OFF_PART + gi] + g_f[OFF_PART + (N2 * 256) + gi]
                + g_f[OFF_PART + 2 * (N2 * 256) + gi] + g_f[OFF_PART + 3 * (N2 * 256) + gi];
        g_f[OFF_T2 + gi] = v;
        sT[ns * 256 + tid] = v;
    }
    __syncthreads();
    int local = tid & 127, sub = tid >> 7;
    int g = local >> 2, b = local & 3;
    float bv = bias2[g];
#pragma unroll
    for (int pass = 0; pass < 4; pass++) {
        int ns = pass * 2 + sub;
        float s = 0.f;
#pragma unroll
        for (int d = 0; d < G1C; d++) s = fmaf(sT[ns * 256 + d * 4 + b], sW[d * G2C + g], s);
        g_f[OFF_Y2 + (n0 + ns) * 128 + local] = s + bv;
    }
}

// fused prop + ein for conv2 step k: packed CSR + 4-deep MLP batching
__global__ void k_step2(int inOff, int outOff, int prevOff, int dbl,
                        const float* __restrict__ W2, int k) {
    __shared__ float sW[G1C * G2C];
    __shared__ float sT[8 * 256];
    int tid = threadIdx.x;
    for (int i = tid; i < G1C * G2C; i += 256) sW[i] = W2[k * G1C * G2C + i];
    int warp = tid >> 5, lane = tid & 31;
    int node = blockIdx.x * 8 + warp;
    int beg = g_i[IO_RP2 + node], end = g_i[IO_RP2 + node + 1];
    const float4* in = (const float4*)(g_f + inOff);
    float4 a0 = make_float4(0.f, 0.f, 0.f, 0.f);
    float4 a1 = a0;
    for (int i = beg; i < end; i += 4) {
        float2 p0 = g_pk2[i];
        float2 p1 = (i + 1 < end) ? g_pk2[i + 1] : make_float2(0.f, __int_as_float(0));
        float2 p2 = (i + 2 < end) ? g_pk2[i + 2] : make_float2(0.f, __int_as_float(0));
        float2 p3 = (i + 3 < end) ? g_pk2[i + 3] : make_float2(0.f, __int_as_float(0));
        const float4* r0 = in + (size_t)__float_as_int(p0.y) * 64;
        const float4* r1 = in + (size_t)__float_as_int(p1.y) * 64;
        const float4* r2 = in + (size_t)__float_as_int(p2.y) * 64;
        const float4* r3 = in + (size_t)__float_as_int(p3.y) * 64;
        float4 v00 = r0[lane], v01 = r0[lane + 32];
        float4 v10 = r1[lane], v11 = r1[lane + 32];
        float4 v20 = r2[lane], v21 = r2[lane + 32];
        float4 v30 = r3[lane], v31 = r3[lane + 32];
        FMA4(a0, p0.x, v00); FMA4(a1, p0.x, v01);
        FMA4(a0, p1.x, v10); FMA4(a1, p1.x, v11);
        FMA4(a0, p2.x, v20); FMA4(a1, p2.x, v21);
        FMA4(a0, p3.x, v30); FMA4(a1, p3.x, v31);
    }
    if (dbl) {
        const float4* pv = (const float4*)(g_f + prevOff) + node * 64;
        float4 p0 = pv[lane], p1 = pv[lane + 32];
        a0.x = 2.f * a0.x - p0.x; a0.y = 2.f * a0.y - p0.y;
        a0.z = 2.f * a0.z - p0.z; a0.w = 2.f * a0.w - p0.w;
        a1.x = 2.f * a1.x - p1.x; a1.y = 2.f * a1.y - p1.y;
        a1.z = 2.f * a1.z - p1.z; a1.w = 2.f * a1.w - p1.w;
    }
    float4* o = (float4*)(g_f + outOff) + node * 64;
    o[lane] = a0;
    o[lane + 32] = a1;
    *(float4*)&sT[warp * 256 + lane * 4] = a0;
    *(float4*)&sT[warp * 256 + 128 + lane * 4] = a1;
    __syncthreads();
    int local = tid & 127, sub = tid >> 7;
    int g = local >> 2, b = local & 3;
    int n0 = blockIdx.x * 8;
#pragma unroll
    for (int pass = 0; pass < 4; pass++) {
        int ns = pass * 2 + sub;
        float s = 0.f;
#pragma unroll
        for (int d = 0; d < G1C; d++) s = fmaf(sT[ns * 256 + d * 4 + b], sW[d * G2C + g], s);
        g_f[OFF_Y2 + (n0 + ns) * 128 + local] += s;
    }
}

// ================= B^T split conversion (relu fused) =================

__global__ void k_convBT() {
    __shared__ float s[64][65];
    int kt = blockIdx.x >> 2, nt = blockIdx.x & 3;
    int k0 = kt * 64, n0 = nt * 64;
    int t = threadIdx.x;
    {
        int r = t >> 4, c4 = t & 15;
#pragma unroll
        for (int i = 0; i < 4; i++) {
            int row = r + i * 16;
            float4 v = *(const float4*)&g_f[OFF_Y1 + (size_t)(k0 + row) * 256 + n0 + c4 * 4];
            s[row][c4 * 4 + 0] = fmaxf(v.x, 0.f);
            s[row][c4 * 4 + 1] = fmaxf(v.y, 0.f);
            s[row][c4 * 4 + 2] = fmaxf(v.z, 0.f);
            s[row][c4 * 4 + 3] = fmaxf(v.w, 0.f);
        }
    }
    __syncthreads();
    int n = t >> 2, kc = t & 3;
    unsigned short h[16], l[16];
#pragma unroll
    for (int e = 0; e < 16; e++) {
        split_bf16(s[kc * 16 + e][n], h[e], l[e]);
    }
    size_t ob = (size_t)(n0 + n) * N1 + k0 + kc * 16;
    uint4* dh = (uint4*)(g_Bthi + ob);
    uint4* dl = (uint4*)(g_Btlo + ob);
#pragma unroll
    for (int half = 0; half < 2; half++) {
        int e0 = half * 8;
        dh[half] = make_uint4((uint32_t)h[e0] | ((uint32_t)h[e0+1] << 16),
                              (uint32_t)h[e0+2] | ((uint32_t)h[e0+3] << 16),
                              (uint32_t)h[e0+4] | ((uint32_t)h[e0+5] << 16),
                              (uint32_t)h[e0+6] | ((uint32_t)h[e0+7] << 16));
        dl[half] = make_uint4((uint32_t)l[e0] | ((uint32_t)l[e0+1] << 16),
                              (uint32_t)l[e0+2] | ((uint32_t)l[e0+3] << 16),
                              (uint32_t)l[e0+4] | ((uint32_t)l[e0+5] << 16),
                              (uint32_t)l[e0+6] | ((uint32_t)l[e0+7] << 16));
    }
}

// ================= mma.sync split-bf16 GEMM (A converted inline) =================

#define SA_H 0
#define SA_L 10240
#define SB_H 20480
#define SB_L 40960
#define GSTAGE 61440
#define GSM_TOTAL (2 * GSTAGE)
#define NKCHUNK 64   // 2048 / 32

__global__ void __launch_bounds__(512, 1) k_gemm_mma(const float* __restrict__ Agl) {
    extern __shared__ char smem[];
    uint32_t sb = smem_u32(smem);
    int tid = threadIdx.x, lane = tid & 31, wid = tid >> 5;
    int mt = blockIdx.x, ks = blockIdx.y;
    int bm = mt * 128;
    int kbase = ks * 2048;

    const __nv_bfloat16* Bh = g_Bthi;
    const __nv_bfloat16* Bl = g_Btlo;

    int arow = tid >> 2, ach = tid & 3;
    int brow = tid >> 1, bch = tid & 1;
    const float* Arow = Agl + (size_t)(bm + arow) * N1 + kbase + ach * 8;

#define LOADB(kc, st) do { \
        int kb_ = kbase + (kc) * 32 + bch * 16; \
        uint32_t db_ = sb + (st) * GSTAGE + brow * 80 + bch * 32; \
        CP16(db_ + SB_H,      Bh + (size_t)brow * N1 + kb_); \
        CP16(db_ + SB_H + 16, Bh + (size_t)brow * N1 + kb_ + 8); \
        CP16(db_ + SB_L,      Bl + (size_t)brow * N1 + kb_); \
        CP16(db_ + SB_L + 16, Bl + (size_t)brow * N1 + kb_ + 8); \
    } while (0)

#define STS_A(v0, v1, st) do { \
        unsigned short h_[8], l_[8]; \
        split_bf16((v0).x, h_[0], l_[0]); split_bf16((v0).y, h_[1], l_[1]); \
        split_bf16((v0).z, h_[2], l_[2]); split_bf16((v0).w, h_[3], l_[3]); \
        split_bf16((v1).x, h_[4], l_[4]); split_bf16((v1).y, h_[5], l_[5]); \
        split_bf16((v1).z, h_[6], l_[6]); split_bf16((v1).w, h_[7], l_[7]); \
        uint32_t da_ = sb + (st) * GSTAGE + arow * 80 + ach * 16; \
        *(uint4*)(smem + (da_ - sb) + SA_H) = make_uint4( \
            (uint32_t)h_[0] | ((uint32_t)h_[1] << 16), (uint32_t)h_[2] | ((uint32_t)h_[3] << 16), \
            (uint32_t)h_[4] | ((uint32_t)h_[5] << 16), (uint32_t)h_[6] | ((uint32_t)h_[7] << 16)); \
        *(uint4*)(smem + (da_ - sb) + SA_L) = make_uint4( \
            (uint32_t)l_[0] | ((uint32_t)l_[1] << 16), (uint32_t)l_[2] | ((uint32_t)l_[3] << 16), \
            (uint32_t)l_[4] | ((uint32_t)l_[5] << 16), (uint32_t)l_[6] | ((uint32_t)l_[7] << 16)); \
    } while (0)

    {
        float4 a0 = *(const float4*)(Arow + 0 * 32);
        float4 a1 = *(const float4*)(Arow + 0 * 32 + 4);
        STS_A(a0, a1, 0);
        float4 b0 = *(const float4*)(Arow + 1 * 32);
        float4 b1 = *(const float4*)(Arow + 1 * 32 + 4);
        STS_A(b0, b1, 1);
    }
    LOADB(0, 0); CP_COMMIT();
    LOADB(1, 1); CP_COMMIT();

    int mw = wid & 3, nw = wid >> 2;
    float acc[2][8][4];
#pragma unroll
    for (int f = 0; f < 2; f++)
#pragma unroll
        for (int g = 0; g < 8; g++)
#pragma unroll
            for (int q = 0; q < 4; q++) acc[f][g][q] = 0.f;

    int qrow = lane >> 2, qk = (lane & 3) * 2;

    for (int kc = 0; kc < NKCHUNK; kc++) {
        int st = kc & 1;
        CP_WAIT1();
        __syncthreads();
        float4 pa0, pa1;
        bool pre = (kc + 2 < NKCHUNK);
        if (pre) {
            pa0 = *(const float4*)(Arow + (kc + 2) * 32);
            pa1 = *(const float4*)(Arow + (kc + 2) * 32 + 4);
        }
        uint32_t base = sb + st * GSTAGE;
#pragma unroll
        for (int kk = 0; kk < 32; kk += 16) {
            uint32_t ah[2][4], al[2][4];
#pragma unroll
            for (int f = 0; f < 2; f++) {
                uint32_t a0 = base + (mw * 32 + f * 16 + qrow) * 80 + (qk + kk) * 2;
                LDS32(ah[f][0], a0 + SA_H);
                LDS32(ah[f][1], a0 + SA_H + 8 * 80);
                LDS32(ah[f][2], a0 + SA_H + 16);
                LDS32(ah[f][3], a0 + SA_H + 8 * 80 + 16);
                LDS32(al[f][0], a0 + SA_L);
                LDS32(al[f][1], a0 + SA_L + 8 * 80);
                LDS32(al[f][2], a0 + SA_L + 16);
                LDS32(al[f][3], a0 + SA_L + 8 * 80 + 16);
            }
#pragma unroll
            for (int g = 0; g < 8; g++) {
                uint32_t bh[2], bl[2];
                uint32_t b0 = base + (nw * 64 + g * 8 + qrow) * 80 + (qk + kk) * 2;
                LDS32(bh[0], b0 + SB_H);
                LDS32(bh[1], b0 + SB_H + 16);
                LDS32(bl[0], b0 + SB_L);
                LDS32(bl[1], b0 + SB_L + 16);
#pragma unroll
                for (int f = 0; f < 2; f++) {
                    MMA_BF16(acc[f][g], ah[f], bh);
                    MMA_BF16(acc[f][g], ah[f], bl);
                    MMA_BF16(acc[f][g], al[f], bh);
                }
            }
        }
        __syncthreads();
        if (pre) {
            STS_A(pa0, pa1, st);
            LOADB(kc + 2, st);
        }
        CP_COMMIT();
    }
#undef LOADB
#undef STS_A

    float* part = g_f + OFF_PART + (size_t)ks * (N2 * 256);
#pragma unroll
    for (int f = 0; f < 2; f++) {
        int row = bm + mw * 32 + f * 16 + qrow;
#pragma unroll
        for (int g = 0; g < 8; g++) {
            int col = nw * 64 + g * 8 + (lane & 3) * 2;
            *(float2*)&part[(size_t)row * 256 + col] = make_float2(acc[f][g][0], acc[f][g][1]);
            *(float2*)&part[(size_t)(row + 8) * 256 + col] = make_float2(acc[f][g][2], acc[f][g][3]);
        }
    }
}

// ================= classifier =================

__global__ void k_fc(const float* __restrict__ fcw) {
    int blk = blockIdx.x;
    int q = blk / 48, rem = blk % 48, c = rem / 8, ks = rem % 8;
    __shared__ float red[256];
    const float4* y = (const float4*)(g_f + OFF_Y2 + (size_t)q * 131072 + ks * 16384);
    const float4* w = (const float4*)(fcw + (size_t)c * 131072 + ks * 16384);
    float s = 0.f;
#pragma unroll
    for (int it = 0; it < 16; it++) {
        int j = it * 256 + threadIdx.x;
        float4 a = y[j], b = w[j];
        s = fmaf(a.x, b.x, s); s = fmaf(a.y, b.y, s);
        s = fmaf(a.z, b.z, s); s = fmaf(a.w, b.w, s);
    }
    red[threadIdx.x] = s;
    __syncthreads();
    for (int o = 128; o > 0; o >>= 1) {
        if (threadIdx.x < o) red[threadIdx.x] += red[threadIdx.x + o];
        __syncthreads();
    }
    if (threadIdx.x == 0) g_f[OFF_FCP + blk] = red[0];
}

__global__ void k_lsm(const float* __restrict__ fcb, float* out) {
    __shared__ float logit[24];
    int t = threadIdx.x;
    if (t < 24) {
        int q = t / 6, c = t % 6;
        float s = fcb[c];
#pragma unroll
        for (int i = 0; i < 8; i++) s += g_f[OFF_FCP + q * 48 + c * 8 + i];
        logit[t] = s;
    }
    __syncwarp();
    if (t < 4) {
        float m = -1e30f;
        for (int c = 0; c < 6; c++) m = fmaxf(m, logit[t * 6 + c]);
        float se = 0.f;
        for (int c = 0; c < 6; c++) se += expf(logit[t * 6 + c] - m);
        float l = logf(se);
        for (int c = 0; c < 6; c++) out[t * 6 + c] = logit[t * 6 + c] - m - l;
    }
}

// ================= host =================

extern "C" void kernel_launch(void* const* d_in, const int* in_sizes, int n_in,
                              void* d_out, int out_size) {
    const float*     x    = (const float*)d_in[0];
    const void*      ei1  = d_in[1];
    const float*     w1e  = (const float*)d_in[2];
    const void*      ei2  = d_in[3];
    const float*     w2e  = (const float*)d_in[4];
    const float*     bmap = (const float*)d_in[5];
    const float*     W1   = (const float*)d_in[6];
    const float*     bias1= (const float*)d_in[7];
    const float*     W2   = (const float*)d_in[8];
    const float*     bias2= (const float*)d_in[9];
    const float*     fcw  = (const float*)d_in[10];
    const float*     fcb  = (const float*)d_in[11];
    float*           out  = (float*)d_out;
    (void)in_sizes; (void)n_in; (void)out_size;

    cudaFuncSetAttribute(k_gemm_mma, cudaFuncAttributeMaxDynamicSharedMemorySize, GSM_TOTAL);

    // --- preprocessing (9 launches) ---
    k_zero<<<(N1 + 255) / 256, 256>>>();
    k_detect<<<(E1C + 255) / 256, 256>>>((const long long*)ei1);
    k_decode2<<<(E1C + E2C + 255) / 256, 256>>>(ei1, ei2);
    k_count2<<<(E1C + E2C + 255) / 256, 256>>>();
    k_scan2<<<2, 1024>>>();
    k_fill2<<<(E1C + E2C + 255) / 256, 256>>>();
    k_sortdeg<<<(N1 + N2 + 127) / 128, 128>>>(w1e, w2e);
    k_norm2<<<(E1C + E2C + 255) / 256, 256>>>(w1e, w2e);
    k_pack<<<(E1C + E2C + 255) / 256, 256>>>();

    // --- conv1: xpose+ein0, then 11 fused prop+ein steps ---
    int b1buf[3] = {OFF_T1, OFF_T1 + T1_STRIDE, OFF_T1 + 2 * T1_STRIDE};
    k_xpose_ein0<<<N1 / 8, 256>>>(x, W1, bias1);
    k_step1<<<N1 / 8, 256>>>(b1buf[0], b1buf[1], 0, 0, W1, 1);
    for (int k = 2; k < KCH; k++) {
        int in = b1buf[(k - 1) % 3], o = b1buf[k % 3], pv = b1buf[(k - 2) % 3];
        k_step1<<<N1 / 8, 256>>>(in, o, pv, 1, W1, k);
    }

    // --- split-bf16 mma GEMM (A converted inline; relu fused into convBT) ---
    k_convBT<<<512, 256>>>();
    dim3 gg(32, 4);
    k_gemm_mma<<<gg, 512, GSM_TOTAL>>>(bmap);

    // --- conv2: reduce+ein0, then 11 fused prop+ein steps ---
    int b2buf[3] = {OFF_T2, OFF_T2 + T2_STRIDE, OFF_T2 + 2 * T2_STRIDE};
    k_red_ein0<<<N2 / 8, 256>>>(W2, bias2);
    k_step2<<<N2 / 8, 256>>>(b2buf[0], b2buf[1], 0, 0, W2, 1);
    for (int k = 2; k < KCH; k++) {
        int in = b2buf[(k - 1) % 3], o = b2buf[k % 3], pv = b2buf[(k - 2) % 3];
        k_step2<<<N2 / 8, 256>>>(in, o, pv, 1, W2, k);
    }

    // --- fc + log_softmax ---
    k_fc<<<192, 256>>>(fcw);
    k_lsm<<<1, 32>>>(fcb, out);
}

// round 14
// speedup vs baseline: 1.0465x; 1.0275x over previous
#include <cuda_runtime.h>
#include <cuda_bf16.h>
#include <cstdint>
#include <stdint.h>
#include <math.h>

// ---------------- problem constants ----------------
#define N1   8192
#define N2   4096
#define TT   15
#define BS   4
#define E1C  131072
#define E2C  65536
#define KCH  12
#define G1C  64
#define G2C  32
#define NC   6

// ---------------- float scratch layout ----------------
#define T1_STRIDE (N1*64)
#define OFF_T1    0
#define OFF_Y1    (OFF_T1 + 3*T1_STRIDE)
#define T2_STRIDE (N2*256)
#define OFF_T2    (OFF_Y1 + N1*256)
#define OFF_Y2    (OFF_T2 + 3*T2_STRIDE)
#define OFF_NORM1 (OFF_Y2 + N2*128)
#define OFF_NORM2 (OFF_NORM1 + E1C)
#define OFF_DEG1  (OFF_NORM2 + E2C)
#define OFF_DEG2  (OFF_DEG1 + N1)
#define OFF_LOG   (OFF_DEG2 + N2)
#define OFF_FCP   (OFF_LOG + 64)
#define OFF_PART  (OFF_FCP + 256)
#define SCRATCH_F (OFF_PART + 4*N2*256)

__device__ __align__(16) float g_f[SCRATCH_F];

// bf16 split buffers for B^T only (A converted inline in the GEMM)
__device__ __align__(16) __nv_bfloat16 g_Bthi[(size_t)256 * N1]; // B^T: [256][8192]
__device__ __align__(16) __nv_bfloat16 g_Btlo[(size_t)256 * N1];

// packed CSR edge data: (norm, src-as-float-bits) in CSR position order
__device__ __align__(16) float2 g_pk1[E1C];
__device__ __align__(16) float2 g_pk2[E2C];

// int64-vs-int32 edge dtype flag: OR-only, converges after first call, replay-stable
__device__ int g_flag = 0;

// ---------------- int scratch layout ----------------
#define IO_RP1   1
#define IO_CU1   (IO_RP1 + N1 + 1)
#define IO_EI1   (IO_CU1 + N1)
#define IO_SRC1  (IO_EI1 + E1C)
#define IO_DST1  (IO_SRC1 + E1C)
#define IO_RP2   (IO_DST1 + E1C)
#define IO_CU2   (IO_RP2 + N2 + 1)
#define IO_EI2   (IO_CU2 + N2)
#define IO_SRC2  (IO_EI2 + E2C)
#define IO_DST2  (IO_SRC2 + E2C)
#define SCRATCH_I (IO_DST2 + E2C)

__device__ int g_i[SCRATCH_I];

// ================= helpers =================

__device__ __forceinline__ uint32_t smem_u32(const void* p) {
    uint32_t a;
    asm("{ .reg .u64 t; cvta.to.shared.u64 t, %1; cvt.u32.u64 %0, t; }" : "=r"(a) : "l"(p));
    return a;
}

#define CP16(dst, src) \
    asm volatile("cp.async.cg.shared.global [%0], [%1], 16;" :: "r"(dst), "l"(src))
#define CP_COMMIT() asm volatile("cp.async.commit_group;" ::: "memory")
#define CP_WAIT1()  asm volatile("cp.async.wait_group 1;" ::: "memory")

#define LDS32(v, a) asm volatile("ld.shared.b32 %0, [%1];" : "=r"(v) : "r"(a))

#define MMA_BF16(c, a, b) \
    asm volatile("mma.sync.aligned.m16n8k16.row.col.f32.bf16.bf16.f32 " \
        "{%0,%1,%2,%3}, {%4,%5,%6,%7}, {%8,%9}, {%0,%1,%2,%3};" \
        : "+f"((c)[0]), "+f"((c)[1]), "+f"((c)[2]), "+f"((c)[3]) \
        : "r"((a)[0]), "r"((a)[1]), "r"((a)[2]), "r"((a)[3]), \
          "r"((b)[0]), "r"((b)[1]))

#define FMA4(acc, nm, v) do { \
    (acc).x = fmaf((nm), (v).x, (acc).x); \
    (acc).y = fmaf((nm), (v).y, (acc).y); \
    (acc).z = fmaf((nm), (v).z, (acc).z); \
    (acc).w = fmaf((nm), (v).w, (acc).w); } while (0)

__device__ __forceinline__ void split_bf16(float v, unsigned short& h, unsigned short& l) {
    h = __bfloat16_as_ushort(__float2bfloat16(v));
    float r = v - __bfloat162float(__ushort_as_bfloat16(h));
    l = __bfloat16_as_ushort(__float2bfloat16(r));
}

// ================= preprocessing (fused, 6 launches) =================

// zero counters + detect int64-vs-int32 (flag is OR-only; module init 0)
__global__ void k_init(const long long* p) {
    int i = blockIdx.x * blockDim.x + threadIdx.x;
    if (i < N1) g_i[IO_CU1 + i] = 0;
    if (i < N2) g_i[IO_CU2 + i] = 0;
    if (i < E1C) {
        long long v = p[i];
        if (v < 0 || v >= (long long)N1) atomicOr(&g_flag, 1);
    }
}

// decode both graphs + count own dst (same-thread data; no cross-thread dep)
__global__ void k_decode_count(const void* ei1, const void* ei2) {
    int e = blockIdx.x * blockDim.x + threadIdx.x;
    int is32 = g_flag;
    const void* eiv; int E, srcOff, dstOff, cuOff, le;
    if (e < E1C) { eiv = ei1; E = E1C; srcOff = IO_SRC1; dstOff = IO_DST1; cuOff = IO_CU1; le = e; }
    else if (e < E1C + E2C) { eiv = ei2; E = E2C; srcOff = IO_SRC2; dstOff = IO_DST2; cuOff = IO_CU2; le = e - E1C; }
    else return;
    int s, d;
    if (is32) {
        const int* p = (const int*)eiv;
        s = p[le]; d = p[E + le];
    } else {
        const long long* p = (const long long*)eiv;
        s = (int)p[le]; d = (int)p[E + le];
    }
    g_i[srcOff + le] = s;
    g_i[dstOff + le] = d;
    atomicAdd(&g_i[cuOff + d], 1);
}

__global__ void k_scan2() {
    __shared__ int part[1024];
    int n, cntOff, rpOff;
    if (blockIdx.x == 0) { n = N1; cntOff = IO_CU1; rpOff = IO_RP1; }
    else                 { n = N2; cntOff = IO_CU2; rpOff = IO_RP2; }
    int t = threadIdx.x;
    int chunk = (n + 1023) >> 10;
    int base = t * chunk;
    int s = 0;
    for (int i = 0; i < chunk; i++) { int idx = base + i; if (idx < n) s += g_i[cntOff + idx]; }
    part[t] = s;
    __syncthreads();
    for (int off = 1; off < 1024; off <<= 1) {
        int v = (t >= off) ? part[t - off] : 0;
        __syncthreads();
        part[t] += v;
        __syncthreads();
    }
    int run = (t > 0) ? part[t - 1] : 0;
    for (int i = 0; i < chunk; i++) {
        int idx = base + i;
        if (idx < n) {
            int v = g_i[cntOff + idx];
            g_i[rpOff + idx] = run;
            g_i[cntOff + idx] = run;
            run += v;
        }
    }
    if (t == 1023) g_i[rpOff + n] = part[1023];
}

__global__ void k_fill2() {
    int e = blockIdx.x * blockDim.x + threadIdx.x;
    if (e < E1C) {
        int d = g_i[IO_DST1 + e];
        int p = atomicAdd(&g_i[IO_CU1 + d], 1);
        g_i[IO_EI1 + p] = e;
    } else if (e < E1C + E2C) {
        int le = e - E1C;
        int d = g_i[IO_DST2 + le];
        int p = atomicAdd(&g_i[IO_CU2 + d], 1);
        g_i[IO_EI2 + p] = le;
    }
}

__global__ void k_sortdeg(const float* w1, const float* w2) {
    int idx = blockIdx.x * blockDim.x + threadIdx.x;
    int rpOff, eidOff, degOff, node;
    const float* w;
    if (idx < N1) { node = idx; rpOff = IO_RP1; eidOff = IO_EI1; degOff = OFF_DEG1; w = w1; }
    else if (idx < N1 + N2) { node = idx - N1; rpOff = IO_RP2; eidOff = IO_EI2; degOff = OFF_DEG2; w = w2; }
    else return;
    int beg = g_i[rpOff + node], end = g_i[rpOff + node + 1];
    for (int i = beg + 1; i < end; i++) {
        int key = g_i[eidOff + i];
        int j = i - 1;
        while (j >= beg && g_i[eidOff + j] > key) {
            g_i[eidOff + j + 1] = g_i[eidOff + j];
            j--;
        }
        g_i[eidOff + j + 1] = key;
    }
    float s = 0.f;
    for (int i = beg; i < end; i++) s += w[g_i[eidOff + i]];
    g_f[degOff + node] = s;
}

// pack (norm, src) in CSR position order; norm computed inline (bit-identical)
__global__ void k_pack_norm(const float* w1, const float* w2) {
    int p = blockIdx.x * blockDim.x + threadIdx.x;
    if (p < E1C) {
        int e = g_i[IO_EI1 + p];
        int s = g_i[IO_SRC1 + e], d = g_i[IO_DST1 + e];
        float ds = g_f[OFF_DEG1 + s];
        float dd = g_f[OFF_DEG1 + d];
        float rs = (ds > 0.f) ? rsqrtf(ds) : 0.f;
        float rd = (dd > 0.f) ? rsqrtf(dd) : 0.f;
        g_pk1[p] = make_float2(-w1[e] * rs * rd, __int_as_float(s));
    } else if (p < E1C + E2C) {
        int lp = p - E1C;
        int e = g_i[IO_EI2 + lp];
        int s = g_i[IO_SRC2 + e], d = g_i[IO_DST2 + e];
        float ds = g_f[OFF_DEG2 + s];
        float dd = g_f[OFF_DEG2 + d];
        float rs = (ds > 0.f) ? rsqrtf(ds) : 0.f;
        float rd = (dd > 0.f) ? rsqrtf(dd) : 0.f;
        g_pk2[lp] = make_float2(-w2[e] * rs * rd, __int_as_float(s));
    }
}

// ================= conv1: fused kernels (exact R9 bodies) =================

__global__ void k_xpose_ein0(const float* __restrict__ x, const float* __restrict__ W1,
                             const float* __restrict__ bias1) {
    __shared__ float sW[TT * G1C];
    __shared__ float sT[8 * 64];
    int tid = threadIdx.x;
    int n0 = blockIdx.x * 8;
    for (int i = tid; i < TT * G1C; i += 256) sW[i] = W1[i];
#pragma unroll
    for (int it = 0; it < 2; it++) {
        int i = it * 256 + tid;
        int ns = i >> 6, j = i & 63;
        int d = j >> 2, b = j & 3;
        float v = (d < TT) ? x[(size_t)b * (N1 * TT) + (n0 + ns) * TT + d] : 0.f;
        sT[i] = v;
        g_f[OFF_T1 + (n0 + ns) * 64 + j] = v;
    }
    __syncthreads();
    int g = tid >> 2, b = tid & 3;
    float bv = bias1[g];
#pragma unroll
    for (int ns = 0; ns < 8; ns++) {
        float s = 0.f;
#pragma unroll
        for (int d = 0; d < TT; d++) s = fmaf(sT[ns * 64 + d * 4 + b], sW[d * G1C + g], s);
        g_f[OFF_Y1 + (n0 + ns) * 256 + tid] = s + bv;
    }
}

// fused prop + ein for conv1 step k (exact R9 body + wr dead-store skip)
__global__ void k_step1(int inOff, int outOff, int prevOff, int dbl,
                        const float* __restrict__ W1, int k, int wr) {
    __shared__ float sW[TT * G1C];
    __shared__ float sT[8 * 64];
    int tid = threadIdx.x;
    for (int i = tid; i < TT * G1C; i += 256) sW[i] = W1[k * TT * G1C + i];
    int warp = tid >> 5, lane = tid & 31;
    int node = blockIdx.x * 8 + warp;
    int half = lane >> 4, c4 = lane & 15;
    int beg = g_i[IO_RP1 + node], end = g_i[IO_RP1 + node + 1];
    const float4* in = (const float4*)(g_f + inOff);
    float4 acc = make_float4(0.f, 0.f, 0.f, 0.f);
    for (int i = beg + half; i < end; i += 8) {
        float2 p0 = g_pk1[i];
        float2 p1 = (i + 2 < end) ? g_pk1[i + 2] : make_float2(0.f, __int_as_float(0));
        float2 p2 = (i + 4 < end) ? g_pk1[i + 4] : make_float2(0.f, __int_as_float(0));
        float2 p3 = (i + 6 < end) ? g_pk1[i + 6] : make_float2(0.f, __int_as_float(0));
        float4 v0 = in[__float_as_int(p0.y) * 16 + c4];
        float4 v1 = in[__float_as_int(p1.y) * 16 + c4];
        float4 v2 = in[__float_as_int(p2.y) * 16 + c4];
        float4 v3 = in[__float_as_int(p3.y) * 16 + c4];
        FMA4(acc, p0.x, v0);
        FMA4(acc, p1.x, v1);
        FMA4(acc, p2.x, v2);
        FMA4(acc, p3.x, v3);
    }
    acc.x += __shfl_down_sync(0xffffffffu, acc.x, 16);
    acc.y += __shfl_down_sync(0xffffffffu, acc.y, 16);
    acc.z += __shfl_down_sync(0xffffffffu, acc.z, 16);
    acc.w += __shfl_down_sync(0xffffffffu, acc.w, 16);
    if (half == 0) {
        float4 r = acc;
        if (dbl) {
            float4 p = ((const float4*)(g_f + prevOff))[node * 16 + c4];
            r.x = 2.f * r.x - p.x;
            r.y = 2.f * r.y - p.y;
            r.z = 2.f * r.z - p.z;
            r.w = 2.f * r.w - p.w;
        }
        if (wr) ((float4*)(g_f + outOff))[node * 16 + c4] = r;
        *(float4*)&sT[warp * 64 + c4 * 4] = r;
    }
    __syncthreads();
    int g = tid >> 2, b = tid & 3;
    int n0 = blockIdx.x * 8;
#pragma unroll
    for (int ns = 0; ns < 8; ns++) {
        float s = 0.f;
#pragma unroll
        for (int d = 0; d < TT; d++) s = fmaf(sT[ns * 64 + d * 4 + b], sW[d * G1C + g], s);
        g_f[OFF_Y1 + (n0 + ns) * 256 + tid] += s;
    }
}

// ================= conv2: fused kernels (exact R9 bodies) =================

__global__ void k_red_ein0(const float* __restrict__ W2, const float* __restrict__ bias2) {
    __shared__ float sW[G1C * G2C];
    __shared__ float sT[8 * 256];
    int tid = threadIdx.x;
    int n0 = blockIdx.x * 8;
    for (int i = tid; i < G1C * G2C; i += 256) sW[i] = W2[i];
#pragma unroll
    for (int ns = 0; ns < 8; ns++) {
        size_t gi = (size_t)(n0 + ns) * 256 + tid;
        float v = g_f[OFF_PART + gi] + g_f[OFF_PART + (N2 * 256) + gi]
                + g_f[OFF_PART + 2 * (N2 * 256) + gi] + g_f[OFF_PART + 3 * (N2 * 256) + gi];
        g_f[OFF_T2 + gi] = v;
        sT[ns * 256 + tid] = v;
    }
    __syncthreads();
    int local = tid & 127, sub = tid >> 7;
    int g = local >> 2, b = local & 3;
    float bv = bias2[g];
#pragma unroll
    for (int pass = 0; pass < 4; pass++) {
        int ns = pass * 2 + sub;
        float s = 0.f;
#pragma unroll
        for (int d = 0; d < G1C; d++) s = fmaf(sT[ns * 256 + d * 4 + b], sW[d * G2C + g], s);
        g_f[OFF_Y2 + (n0 + ns) * 128 + local] = s + bv;
    }
}

// fused prop + ein for conv2 step k (exact R9 body + wr dead-store skip)
__global__ void k_step2(int inOff, int outOff, int prevOff, int dbl,
                        const float* __restrict__ W2, int k, int wr) {
    __shared__ float sW[G1C * G2C];
    __shared__ float sT[8 * 256];
    int tid = threadIdx.x;
    for (int i = tid; i < G1C * G2C; i += 256) sW[i] = W2[k * G1C * G2C + i];
    int warp = tid >> 5, lane = tid & 31;
    int node = blockIdx.x * 8 + warp;
    int beg = g_i[IO_RP2 + node], end = g_i[IO_RP2 + node + 1];
    const float4* in = (const float4*)(g_f + inOff);
    float4 a0 = make_float4(0.f, 0.f, 0.f, 0.f);
    float4 a1 = a0;
    for (int i = beg; i < end; i += 4) {
        float2 p0 = g_pk2[i];
        float2 p1 = (i + 1 < end) ? g_pk2[i + 1] : make_float2(0.f, __int_as_float(0));
        float2 p2 = (i + 2 < end) ? g_pk2[i + 2] : make_float2(0.f, __int_as_float(0));
        float2 p3 = (i + 3 < end) ? g_pk2[i + 3] : make_float2(0.f, __int_as_float(0));
        const float4* r0 = in + (size_t)__float_as_int(p0.y) * 64;
        const float4* r1 = in + (size_t)__float_as_int(p1.y) * 64;
        const float4* r2 = in + (size_t)__float_as_int(p2.y) * 64;
        const float4* r3 = in + (size_t)__float_as_int(p3.y) * 64;
        float4 v00 = r0[lane], v01 = r0[lane + 32];
        float4 v10 = r1[lane], v11 = r1[lane + 32];
        float4 v20 = r2[lane], v21 = r2[lane + 32];
        float4 v30 = r3[lane], v31 = r3[lane + 32];
        FMA4(a0, p0.x, v00); FMA4(a1, p0.x, v01);
        FMA4(a0, p1.x, v10); FMA4(a1, p1.x, v11);
        FMA4(a0, p2.x, v20); FMA4(a1, p2.x, v21);
        FMA4(a0, p3.x, v30); FMA4(a1, p3.x, v31);
    }
    if (dbl) {
        const float4* pv = (const float4*)(g_f + prevOff) + node * 64;
        float4 p0 = pv[lane], p1 = pv[lane + 32];
        a0.x = 2.f * a0.x - p0.x; a0.y = 2.f * a0.y - p0.y;
        a0.z = 2.f * a0.z - p0.z; a0.w = 2.f * a0.w - p0.w;
        a1.x = 2.f * a1.x - p1.x; a1.y = 2.f * a1.y - p1.y;
        a1.z = 2.f * a1.z - p1.z; a1.w = 2.f * a1.w - p1.w;
    }
    if (wr) {
        float4* o = (float4*)(g_f + outOff) + node * 64;
        o[lane] = a0;
        o[lane + 32] = a1;
    }
    *(float4*)&sT[warp * 256 + lane * 4] = a0;
    *(float4*)&sT[warp * 256 + 128 + lane * 4] = a1;
    __syncthreads();
    int local = tid & 127, sub = tid >> 7;
    int g = local >> 2, b = local & 3;
    int n0 = blockIdx.x * 8;
#pragma unroll
    for (int pass = 0; pass < 4; pass++) {
        int ns = pass * 2 + sub;
        float s = 0.f;
#pragma unroll
        for (int d = 0; d < G1C; d++) s = fmaf(sT[ns * 256 + d * 4 + b], sW[d * G2C + g], s);
        g_f[OFF_Y2 + (n0 + ns) * 128 + local] += s;
    }
}

// ================= B^T split conversion (relu fused) =================

__global__ void k_convBT() {
    __shared__ float s[64][65];
    int kt = blockIdx.x >> 2, nt = blockIdx.x & 3;
    int k0 = kt * 64, n0 = nt * 64;
    int t = threadIdx.x;
    {
        int r = t >> 4, c4 = t & 15;
#pragma unroll
        for (int i = 0; i < 4; i++) {
            int row = r + i * 16;
            float4 v = *(const float4*)&g_f[OFF_Y1 + (size_t)(k0 + row) * 256 + n0 + c4 * 4];
            s[row][c4 * 4 + 0] = fmaxf(v.x, 0.f);
            s[row][c4 * 4 + 1] = fmaxf(v.y, 0.f);
            s[row][c4 * 4 + 2] = fmaxf(v.z, 0.f);
            s[row][c4 * 4 + 3] = fmaxf(v.w, 0.f);
        }
    }
    __syncthreads();
    int n = t >> 2, kc = t & 3;
    unsigned short h[16], l[16];
#pragma unroll
    for (int e = 0; e < 16; e++) {
        split_bf16(s[kc * 16 + e][n], h[e], l[e]);
    }
    size_t ob = (size_t)(n0 + n) * N1 + k0 + kc * 16;
    uint4* dh = (uint4*)(g_Bthi + ob);
    uint4* dl = (uint4*)(g_Btlo + ob);
#pragma unroll
    for (int half = 0; half < 2; half++) {
        int e0 = half * 8;
        dh[half] = make_uint4((uint32_t)h[e0] | ((uint32_t)h[e0+1] << 16),
                              (uint32_t)h[e0+2] | ((uint32_t)h[e0+3] << 16),
                              (uint32_t)h[e0+4] | ((uint32_t)h[e0+5] << 16),
                              (uint32_t)h[e0+6] | ((uint32_t)h[e0+7] << 16));
        dl[half] = make_uint4((uint32_t)l[e0] | ((uint32_t)l[e0+1] << 16),
                              (uint32_t)l[e0+2] | ((uint32_t)l[e0+3] << 16),
                              (uint32_t)l[e0+4] | ((uint32_t)l[e0+5] << 16),
                              (uint32_t)l[e0+6] | ((uint32_t)l[e0+7] << 16));
    }
}

// ================= mma.sync split-bf16 GEMM (A converted inline) =================

#define SA_H 0
#define SA_L 10240
#define SB_H 20480
#define SB_L 40960
#define GSTAGE 61440
#define GSM_TOTAL (2 * GSTAGE)
#define NKCHUNK 64   // 2048 / 32

__global__ void __launch_bounds__(512, 1) k_gemm_mma(const float* __restrict__ Agl) {
    extern __shared__ char smem[];
    uint32_t sb = smem_u32(smem);
    int tid = threadIdx.x, lane = tid & 31, wid = tid >> 5;
    int mt = blockIdx.x, ks = blockIdx.y;
    int bm = mt * 128;
    int kbase = ks * 2048;

    const __nv_bfloat16* Bh = g_Bthi;
    const __nv_bfloat16* Bl = g_Btlo;

    int arow = tid >> 2, ach = tid & 3;
    int brow = tid >> 1, bch = tid & 1;
    const float* Arow = Agl + (size_t)(bm + arow) * N1 + kbase + ach * 8;

#define LOADB(kc, st) do { \
        int kb_ = kbase + (kc) * 32 + bch * 16; \
        uint32_t db_ = sb + (st) * GSTAGE + brow * 80 + bch * 32; \
        CP16(db_ + SB_H,      Bh + (size_t)brow * N1 + kb_); \
        CP16(db_ + SB_H + 16, Bh + (size_t)brow * N1 + kb_ + 8); \
        CP16(db_ + SB_L,      Bl + (size_t)brow * N1 + kb_); \
        CP16(db_ + SB_L + 16, Bl + (size_t)brow * N1 + kb_ + 8); \
    } while (0)

#define STS_A(v0, v1, st) do { \
        unsigned short h_[8], l_[8]; \
        split_bf16((v0).x, h_[0], l_[0]); split_bf16((v0).y, h_[1], l_[1]); \
        split_bf16((v0).z, h_[2], l_[2]); split_bf16((v0).w, h_[3], l_[3]); \
        split_bf16((v1).x, h_[4], l_[4]); split_bf16((v1).y, h_[5], l_[5]); \
        split_bf16((v1).z, h_[6], l_[6]); split_bf16((v1).w, h_[7], l_[7]); \
        uint32_t da_ = sb + (st) * GSTAGE + arow * 80 + ach * 16; \
        *(uint4*)(smem + (da_ - sb) + SA_H) = make_uint4( \
            (uint32_t)h_[0] | ((uint32_t)h_[1] << 16), (uint32_t)h_[2] | ((uint32_t)h_[3] << 16), \
            (uint32_t)h_[4] | ((uint32_t)h_[5] << 16), (uint32_t)h_[6] | ((uint32_t)h_[7] << 16)); \
        *(uint4*)(smem + (da_ - sb) + SA_L) = make_uint4( \
            (uint32_t)l_[0] | ((uint32_t)l_[1] << 16), (uint32_t)l_[2] | ((uint32_t)l_[3] << 16), \
            (uint32_t)l_[4] | ((uint32_t)l_[5] << 16), (uint32_t)l_[6] | ((uint32_t)l_[7] << 16)); \
    } while (0)

    {
        float4 a0 = *(const float4*)(Arow + 0 * 32);
        float4 a1 = *(const float4*)(Arow + 0 * 32 + 4);
        STS_A(a0, a1, 0);
        float4 b0 = *(const float4*)(Arow + 1 * 32);
        float4 b1 = *(const float4*)(Arow + 1 * 32 + 4);
        STS_A(b0, b1, 1);
    }
    LOADB(0, 0); CP_COMMIT();
    LOADB(1, 1); CP_COMMIT();

    int mw = wid & 3, nw = wid >> 2;
    float acc[2][8][4];
#pragma unroll
    for (int f = 0; f < 2; f++)
#pragma unroll
        for (int g = 0; g < 8; g++)
#pragma unroll
            for (int q = 0; q < 4; q++) acc[f][g][q] = 0.f;

    int qrow = lane >> 2, qk = (lane & 3) * 2;

    for (int kc = 0; kc < NKCHUNK; kc++) {
        int st = kc & 1;
        CP_WAIT1();
        __syncthreads();
        float4 pa0, pa1;
        bool pre = (kc + 2 < NKCHUNK);
        if (pre) {
            pa0 = *(const float4*)(Arow + (kc + 2) * 32);
            pa1 = *(const float4*)(Arow + (kc + 2) * 32 + 4);
        }
        uint32_t base = sb + st * GSTAGE;
#pragma unroll
        for (int kk = 0; kk < 32; kk += 16) {
            uint32_t ah[2][4], al[2][4];
#pragma unroll
            for (int f = 0; f < 2; f++) {
                uint32_t a0 = base + (mw * 32 + f * 16 + qrow) * 80 + (qk + kk) * 2;
                LDS32(ah[f][0], a0 + SA_H);
                LDS32(ah[f][1], a0 + SA_H + 8 * 80);
                LDS32(ah[f][2], a0 + SA_H + 16);
                LDS32(ah[f][3], a0 + SA_H + 8 * 80 + 16);
                LDS32(al[f][0], a0 + SA_L);
                LDS32(al[f][1], a0 + SA_L + 8 * 80);
                LDS32(al[f][2], a0 + SA_L + 16);
                LDS32(al[f][3], a0 + SA_L + 8 * 80 + 16);
            }
#pragma unroll
            for (int g = 0; g < 8; g++) {
                uint32_t bh[2], bl[2];
                uint32_t b0 = base + (nw * 64 + g * 8 + qrow) * 80 + (qk + kk) * 2;
                LDS32(bh[0], b0 + SB_H);
                LDS32(bh[1], b0 + SB_H + 16);
                LDS32(bl[0], b0 + SB_L);
                LDS32(bl[1], b0 + SB_L + 16);
#pragma unroll
                for (int f = 0; f < 2; f++) {
                    MMA_BF16(acc[f][g], ah[f], bh);
                    MMA_BF16(acc[f][g], ah[f], bl);
                    MMA_BF16(acc[f][g], al[f], bh);
                }
            }
        }
        __syncthreads();
        if (pre) {
            STS_A(pa0, pa1, st);
            LOADB(kc + 2, st);
        }
        CP_COMMIT();
    }
#undef LOADB
#undef STS_A

    float* part = g_f + OFF_PART + (size_t)ks * (N2 * 256);
#pragma unroll
    for (int f = 0; f < 2; f++) {
        int row = bm + mw * 32 + f * 16 + qrow;
#pragma unroll
        for (int g = 0; g < 8; g++) {
            int col = nw * 64 + g * 8 + (lane & 3) * 2;
            *(float2*)&part[(size_t)row * 256 + col] = make_float2(acc[f][g][0], acc[f][g][1]);
            *(float2*)&part[(size_t)(row + 8) * 256 + col] = make_float2(acc[f][g][2], acc[f][g][3]);
        }
    }
}

// ================= classifier =================

__global__ void k_fc(const float* __restrict__ fcw) {
    int blk = blockIdx.x;
    int q = blk / 48, rem = blk % 48, c = rem / 8, ks = rem % 8;
    __shared__ float red[256];
    const float4* y = (const float4*)(g_f + OFF_Y2 + (size_t)q * 131072 + ks * 16384);
    const float4* w = (const float4*)(fcw + (size_t)c * 131072 + ks * 16384);
    float s = 0.f;
#pragma unroll
    for (int it = 0; it < 16; it++) {
        int j = it * 256 + threadIdx.x;
        float4 a = y[j], b = w[j];
        s = fmaf(a.x, b.x, s); s = fmaf(a.y, b.y, s);
        s = fmaf(a.z, b.z, s); s = fmaf(a.w, b.w, s);
    }
    red[threadIdx.x] = s;
    __syncthreads();
    for (int o = 128; o > 0; o >>= 1) {
        if (threadIdx.x < o) red[threadIdx.x] += red[threadIdx.x + o];
        __syncthreads();
    }
    if (threadIdx.x == 0) g_f[OFF_FCP + blk] = red[0];
}

__global__ void k_lsm(const float* __restrict__ fcb, float* out) {
    __shared__ float logit[24];
    int t = threadIdx.x;
    if (t < 24) {
        int q = t / 6, c = t % 6;
        float s = fcb[c];
#pragma unroll
        for (int i = 0; i < 8; i++) s += g_f[OFF_FCP + q * 48 + c * 8 + i];
        logit[t] = s;
    }
    __syncwarp();
    if (t < 4) {
        float m = -1e30f;
        for (int c = 0; c < 6; c++) m = fmaxf(m, logit[t * 6 + c]);
        float se = 0.f;
        for (int c = 0; c < 6; c++) se += expf(logit[t * 6 + c] - m);
        float l = logf(se);
        for (int c = 0; c < 6; c++) out[t * 6 + c] = logit[t * 6 + c] - m - l;
    }
}

// ================= host =================

extern "C" void kernel_launch(void* const* d_in, const int* in_sizes, int n_in,
                              void* d_out, int out_size) {
    const float*     x    = (const float*)d_in[0];
    const void*      ei1  = d_in[1];
    const float*     w1e  = (const float*)d_in[2];
    const void*      ei2  = d_in[3];
    const float*     w2e  = (const float*)d_in[4];
    const float*     bmap = (const float*)d_in[5];
    const float*     W1   = (const float*)d_in[6];
    const float*     bias1= (const float*)d_in[7];
    const float*     W2   = (const float*)d_in[8];
    const float*     bias2= (const float*)d_in[9];
    const float*     fcw  = (const float*)d_in[10];
    const float*     fcb  = (const float*)d_in[11];
    float*           out  = (float*)d_out;
    (void)in_sizes; (void)n_in; (void)out_size;

    cudaFuncSetAttribute(k_gemm_mma, cudaFuncAttributeMaxDynamicSharedMemorySize, GSM_TOTAL);

    // --- preprocessing (6 launches) ---
    k_init<<<(E1C + 255) / 256, 256>>>((const long long*)ei1);
    k_decode_count<<<(E1C + E2C + 255) / 256, 256>>>(ei1, ei2);
    k_scan2<<<2, 1024>>>();
    k_fill2<<<(E1C + E2C + 255) / 256, 256>>>();
    k_sortdeg<<<(N1 + N2 + 127) / 128, 128>>>(w1e, w2e);
    k_pack_norm<<<(E1C + E2C + 255) / 256, 256>>>(w1e, w2e);

    // --- conv1: xpose+ein0, then 11 fused prop+ein steps ---
    int b1buf[3] = {OFF_T1, OFF_T1 + T1_STRIDE, OFF_T1 + 2 * T1_STRIDE};
    k_xpose_ein0<<<N1 / 8, 256>>>(x, W1, bias1);
    k_step1<<<N1 / 8, 256>>>(b1buf[0], b1buf[1], 0, 0, W1, 1, 1);
    for (int k = 2; k < KCH; k++) {
        int in = b1buf[(k - 1) % 3], o = b1buf[k % 3], pv = b1buf[(k - 2) % 3];
        k_step1<<<N1 / 8, 256>>>(in, o, pv, 1, W1, k, (k < KCH - 1) ? 1 : 0);
    }

    // --- split-bf16 mma GEMM (A converted inline; relu fused into convBT) ---
    k_convBT<<<512, 256>>>();
    dim3 gg(32, 4);
    k_gemm_mma<<<gg, 512, GSM_TOTAL>>>(bmap);

    // --- conv2: reduce+ein0, then 11 fused prop+ein steps ---
    int b2buf[3] = {OFF_T2, OFF_T2 + T2_STRIDE, OFF_T2 + 2 * T2_STRIDE};
    k_red_ein0<<<N2 / 8, 256>>>(W2, bias2);
    k_step2<<<N2 / 8, 256>>>(b2buf[0], b2buf[1], 0, 0, W2, 1, 1);
    for (int k = 2; k < KCH; k++) {
        int in = b2buf[(k - 1) % 3], o = b2buf[k % 3], pv = b2buf[(k - 2) % 3];
        k_step2<<<N2 / 8, 256>>>(in, o, pv, 1, W2, k, (k < KCH - 1) ? 1 : 0);
    }

    // --- fc + log_softmax ---
    k_fc<<<192, 256>>>(fcw);
    k_lsm<<<1, 32>>>(fcb, out);
}

// round 15
// speedup vs baseline: 1.0488x; 1.0022x over previous
#include <cuda_runtime.h>
#include <cuda_bf16.h>
#include <cstdint>
#include <stdint.h>
#include <math.h>

// ---------------- problem constants ----------------
#define N1   8192
#define N2   4096
#define TT   15
#define BS   4
#define E1C  131072
#define E2C  65536
#define KCH  12
#define G1C  64
#define G2C  32
#define NC   6

// ---------------- float scratch layout ----------------
#define T1_STRIDE (N1*64)
#define OFF_T1    0
// 12 T1 buffers (one per Chebyshev order) for the hoisted conv1 einsum
#define OFF_Y1    (OFF_T1 + 12*T1_STRIDE)
#define T2_STRIDE (N2*256)
#define OFF_T2    (OFF_Y1 + N1*256)
#define OFF_Y2    (OFF_T2 + 3*T2_STRIDE)
#define OFF_DEG1  (OFF_Y2 + N2*128)
#define OFF_DEG2  (OFF_DEG1 + N1)
#define OFF_LOG   (OFF_DEG2 + N2)
#define OFF_FCP   (OFF_LOG + 64)
#define OFF_PART  (OFF_FCP + 256)
#define SCRATCH_F (OFF_PART + 4*N2*256)

__device__ __align__(16) float g_f[SCRATCH_F];

// bf16 split buffers for B^T only (A converted inline in the GEMM)
__device__ __align__(16) __nv_bfloat16 g_Bthi[(size_t)256 * N1]; // B^T: [256][8192]
__device__ __align__(16) __nv_bfloat16 g_Btlo[(size_t)256 * N1];

// packed CSR edge data: (norm, src-as-float-bits) in CSR position order
__device__ __align__(16) float2 g_pk1[E1C];
__device__ __align__(16) float2 g_pk2[E2C];

// int64-vs-int32 edge dtype flag: OR-only, converges after first call, replay-stable
__device__ int g_flag = 0;

// ---------------- int scratch layout ----------------
#define IO_RP1   1
#define IO_CU1   (IO_RP1 + N1 + 1)
#define IO_EI1   (IO_CU1 + N1)
#define IO_SRC1  (IO_EI1 + E1C)
#define IO_DST1  (IO_SRC1 + E1C)
#define IO_RP2   (IO_DST1 + E1C)
#define IO_CU2   (IO_RP2 + N2 + 1)
#define IO_EI2   (IO_CU2 + N2)
#define IO_SRC2  (IO_EI2 + E2C)
#define IO_DST2  (IO_SRC2 + E2C)
#define SCRATCH_I (IO_DST2 + E2C)

__device__ int g_i[SCRATCH_I];

// ================= helpers =================

__device__ __forceinline__ uint32_t smem_u32(const void* p) {
    uint32_t a;
    asm("{ .reg .u64 t; cvta.to.shared.u64 t, %1; cvt.u32.u64 %0, t; }" : "=r"(a) : "l"(p));
    return a;
}

#define CP16(dst, src) \
    asm volatile("cp.async.cg.shared.global [%0], [%1], 16;" :: "r"(dst), "l"(src))
#define CP_COMMIT() asm volatile("cp.async.commit_group;" ::: "memory")
#define CP_WAIT1()  asm volatile("cp.async.wait_group 1;" ::: "memory")

#define LDS32(v, a) asm volatile("ld.shared.b32 %0, [%1];" : "=r"(v) : "r"(a))

#define MMA_BF16(c, a, b) \
    asm volatile("mma.sync.aligned.m16n8k16.row.col.f32.bf16.bf16.f32 " \
        "{%0,%1,%2,%3}, {%4,%5,%6,%7}, {%8,%9}, {%0,%1,%2,%3};" \
        : "+f"((c)[0]), "+f"((c)[1]), "+f"((c)[2]), "+f"((c)[3]) \
        : "r"((a)[0]), "r"((a)[1]), "r"((a)[2]), "r"((a)[3]), \
          "r"((b)[0]), "r"((b)[1]))

#define FMA4(acc, nm, v) do { \
    (acc).x = fmaf((nm), (v).x, (acc).x); \
    (acc).y = fmaf((nm), (v).y, (acc).y); \
    (acc).z = fmaf((nm), (v).z, (acc).z); \
    (acc).w = fmaf((nm), (v).w, (acc).w); } while (0)

__device__ __forceinline__ void split_bf16(float v, unsigned short& h, unsigned short& l) {
    h = __bfloat16_as_ushort(__float2bfloat16(v));
    float r = v - __bfloat162float(__ushort_as_bfloat16(h));
    l = __bfloat16_as_ushort(__float2bfloat16(r));
}

// ================= preprocessing (fused, 6 launches) =================

__global__ void k_init(const long long* p) {
    int i = blockIdx.x * blockDim.x + threadIdx.x;
    if (i < N1) g_i[IO_CU1 + i] = 0;
    if (i < N2) g_i[IO_CU2 + i] = 0;
    if (i < E1C) {
        long long v = p[i];
        if (v < 0 || v >= (long long)N1) atomicOr(&g_flag, 1);
    }
}

__global__ void k_decode_count(const void* ei1, const void* ei2) {
    int e = blockIdx.x * blockDim.x + threadIdx.x;
    int is32 = g_flag;
    const void* eiv; int E, srcOff, dstOff, cuOff, le;
    if (e < E1C) { eiv = ei1; E = E1C; srcOff = IO_SRC1; dstOff = IO_DST1; cuOff = IO_CU1; le = e; }
    else if (e < E1C + E2C) { eiv = ei2; E = E2C; srcOff = IO_SRC2; dstOff = IO_DST2; cuOff = IO_CU2; le = e - E1C; }
    else return;
    int s, d;
    if (is32) {
        const int* p = (const int*)eiv;
        s = p[le]; d = p[E + le];
    } else {
        const long long* p = (const long long*)eiv;
        s = (int)p[le]; d = (int)p[E + le];
    }
    g_i[srcOff + le] = s;
    g_i[dstOff + le] = d;
    atomicAdd(&g_i[cuOff + d], 1);
}

__global__ void k_scan2() {
    __shared__ int part[1024];
    int n, cntOff, rpOff;
    if (blockIdx.x == 0) { n = N1; cntOff = IO_CU1; rpOff = IO_RP1; }
    else                 { n = N2; cntOff = IO_CU2; rpOff = IO_RP2; }
    int t = threadIdx.x;
    int chunk = (n + 1023) >> 10;
    int base = t * chunk;
    int s = 0;
    for (int i = 0; i < chunk; i++) { int idx = base + i; if (idx < n) s += g_i[cntOff + idx]; }
    part[t] = s;
    __syncthreads();
    for (int off = 1; off < 1024; off <<= 1) {
        int v = (t >= off) ? part[t - off] : 0;
        __syncthreads();
        part[t] += v;
        __syncthreads();
    }
    int run = (t > 0) ? part[t - 1] : 0;
    for (int i = 0; i < chunk; i++) {
        int idx = base + i;
        if (idx < n) {
            int v = g_i[cntOff + idx];
            g_i[rpOff + idx] = run;
            g_i[cntOff + idx] = run;
            run += v;
        }
    }
    if (t == 1023) g_i[rpOff + n] = part[1023];
}

__global__ void k_fill2() {
    int e = blockIdx.x * blockDim.x + threadIdx.x;
    if (e < E1C) {
        int d = g_i[IO_DST1 + e];
        int p = atomicAdd(&g_i[IO_CU1 + d], 1);
        g_i[IO_EI1 + p] = e;
    } else if (e < E1C + E2C) {
        int le = e - E1C;
        int d = g_i[IO_DST2 + le];
        int p = atomicAdd(&g_i[IO_CU2 + d], 1);
        g_i[IO_EI2 + p] = le;
    }
}

__global__ void k_sortdeg(const float* w1, const float* w2) {
    int idx = blockIdx.x * blockDim.x + threadIdx.x;
    int rpOff, eidOff, degOff, node;
    const float* w;
    if (idx < N1) { node = idx; rpOff = IO_RP1; eidOff = IO_EI1; degOff = OFF_DEG1; w = w1; }
    else if (idx < N1 + N2) { node = idx - N1; rpOff = IO_RP2; eidOff = IO_EI2; degOff = OFF_DEG2; w = w2; }
    else return;
    int beg = g_i[rpOff + node], end = g_i[rpOff + node + 1];
    for (int i = beg + 1; i < end; i++) {
        int key = g_i[eidOff + i];
        int j = i - 1;
        while (j >= beg && g_i[eidOff + j] > key) {
            g_i[eidOff + j + 1] = g_i[eidOff + j];
            j--;
        }
        g_i[eidOff + j + 1] = key;
    }
    float s = 0.f;
    for (int i = beg; i < end; i++) s += w[g_i[eidOff + i]];
    g_f[degOff + node] = s;
}

__global__ void k_pack_norm(const float* w1, const float* w2) {
    int p = blockIdx.x * blockDim.x + threadIdx.x;
    if (p < E1C) {
        int e = g_i[IO_EI1 + p];
        int s = g_i[IO_SRC1 + e], d = g_i[IO_DST1 + e];
        float ds = g_f[OFF_DEG1 + s];
        float dd = g_f[OFF_DEG1 + d];
        float rs = (ds > 0.f) ? rsqrtf(ds) : 0.f;
        float rd = (dd > 0.f) ? rsqrtf(dd) : 0.f;
        g_pk1[p] = make_float2(-w1[e] * rs * rd, __int_as_float(s));
    } else if (p < E1C + E2C) {
        int lp = p - E1C;
        int e = g_i[IO_EI2 + lp];
        int s = g_i[IO_SRC2 + e], d = g_i[IO_DST2 + e];
        float ds = g_f[OFF_DEG2 + s];
        float dd = g_f[OFF_DEG2 + d];
        float rs = (ds > 0.f) ? rsqrtf(ds) : 0.f;
        float rd = (dd > 0.f) ? rsqrtf(dd) : 0.f;
        g_pk2[lp] = make_float2(-w2[e] * rs * rd, __int_as_float(s));
    }
}

// ================= conv1: gather-only props + hoisted einsum =================

// x (B,N1,T) -> T1[0] (N1, 64), j = d*4+b, d>=15 zero-padded
__global__ void k_xpose(const float* __restrict__ x) {
    int tid = threadIdx.x;
    int n0 = blockIdx.x * 8;
#pragma unroll
    for (int it = 0; it < 2; it++) {
        int i = it * 256 + tid;
        int ns = i >> 6, j = i & 63;
        int d = j >> 2, b = j & 3;
        float v = (d < TT) ? x[(size_t)b * (N1 * TT) + (n0 + ns) * TT + d] : 0.f;
        g_f[OFF_T1 + (n0 + ns) * 64 + j] = v;
    }
}

// gather-only Chebyshev step for conv1 (strict subset of proven R14 k_step1)
__global__ void k_prop1(int inOff, int outOff, int prevOff, int dbl) {
    int tid = threadIdx.x;
    int warp = tid >> 5, lane = tid & 31;
    int node = blockIdx.x * 8 + warp;
    int half = lane >> 4, c4 = lane & 15;
    int beg = g_i[IO_RP1 + node], end = g_i[IO_RP1 + node + 1];
    const float4* in = (const float4*)(g_f + inOff);
    float4 acc = make_float4(0.f, 0.f, 0.f, 0.f);
    for (int i = beg + half; i < end; i += 8) {
        float2 p0 = g_pk1[i];
        float2 p1 = (i + 2 < end) ? g_pk1[i + 2] : make_float2(0.f, __int_as_float(0));
        float2 p2 = (i + 4 < end) ? g_pk1[i + 4] : make_float2(0.f, __int_as_float(0));
        float2 p3 = (i + 6 < end) ? g_pk1[i + 6] : make_float2(0.f, __int_as_float(0));
        float4 v0 = in[__float_as_int(p0.y) * 16 + c4];
        float4 v1 = in[__float_as_int(p1.y) * 16 + c4];
        float4 v2 = in[__float_as_int(p2.y) * 16 + c4];
        float4 v3 = in[__float_as_int(p3.y) * 16 + c4];
        FMA4(acc, p0.x, v0);
        FMA4(acc, p1.x, v1);
        FMA4(acc, p2.x, v2);
        FMA4(acc, p3.x, v3);
    }
    acc.x += __shfl_down_sync(0xffffffffu, acc.x, 16);
    acc.y += __shfl_down_sync(0xffffffffu, acc.y, 16);
    acc.z += __shfl_down_sync(0xffffffffu, acc.z, 16);
    acc.w += __shfl_down_sync(0xffffffffu, acc.w, 16);
    if (half == 0) {
        float4 r = acc;
        if (dbl) {
            float4 p = ((const float4*)(g_f + prevOff))[node * 16 + c4];
            r.x = 2.f * r.x - p.x;
            r.y = 2.f * r.y - p.y;
            r.z = 2.f * r.z - p.z;
            r.w = 2.f * r.w - p.w;
        }
        ((float4*)(g_f + outOff))[node * 16 + c4] = r;
    }
}

// hoisted conv1 einsum: y1 = bias + sum_k T1[k] . W1[k]; y in registers across k.
// Same arithmetic order per element as the distributed version (per-k partial then add).
__global__ void k_ein1_all(const float* __restrict__ W1, const float* __restrict__ bias1) {
    __shared__ float sW[TT * G1C];
    __shared__ float sT[8 * 64];
    int tid = threadIdx.x;
    int n0 = blockIdx.x * 8;
    int g = tid >> 2, b = tid & 3;
    float y[8];
    float bv = bias1[g];
#pragma unroll
    for (int ns = 0; ns < 8; ns++) y[ns] = bv;
    for (int k = 0; k < KCH; k++) {
        __syncthreads();  // guard reuse of sW/sT from previous iteration
        for (int i = tid; i < TT * G1C; i += 256) sW[i] = W1[k * TT * G1C + i];
        sT[tid]       = g_f[OFF_T1 + k * T1_STRIDE + n0 * 64 + tid];
        sT[tid + 256] = g_f[OFF_T1 + k * T1_STRIDE + n0 * 64 + tid + 256];
        __syncthreads();
#pragma unroll
        for (int ns = 0; ns < 8; ns++) {
            float s = 0.f;
#pragma unroll
            for (int d = 0; d < TT; d++) s = fmaf(sT[ns * 64 + d * 4 + b], sW[d * G1C + g], s);
            y[ns] += s;
        }
    }
#pragma unroll
    for (int ns = 0; ns < 8; ns++)
        g_f[OFF_Y1 + (size_t)(n0 + ns) * 256 + tid] = y[ns];
}

// ================= conv2: fused kernels (exact R14 bodies) =================

__global__ void k_red_ein0(const float* __restrict__ W2, const float* __restrict__ bias2) {
    __shared__ float sW[G1C * G2C];
    __shared__ float sT[8 * 256];
    int tid = threadIdx.x;
    int n0 = blockIdx.x * 8;
    for (int i = tid; i < G1C * G2C; i += 256) sW[i] = W2[i];
#pragma unroll
    for (int ns = 0; ns < 8; ns++) {
        size_t gi = (size_t)(n0 + ns) * 256 + tid;
        float v = g_f[OFF_PART + gi] + g_f[OFF_PART + (N2 * 256) + gi]
                + g_f[OFF_PART + 2 * (N2 * 256) + gi] + g_f[OFF_PART + 3 * (N2 * 256) + gi];
        g_f[OFF_T2 + gi] = v;
        sT[ns * 256 + tid] = v;
    }
    __syncthreads();
    int local = tid & 127, sub = tid >> 7;
    int g = local >> 2, b = local & 3;
    float bv = bias2[g];
#pragma unroll
    for (int pass = 0; pass < 4; pass++) {
        int ns = pass * 2 + sub;
        float s = 0.f;
#pragma unroll
        for (int d = 0; d < G1C; d++) s = fmaf(sT[ns * 256 + d * 4 + b], sW[d * G2C + g], s);
        g_f[OFF_Y2 + (n0 + ns) * 128 + local] = s + bv;
    }
}

__global__ void k_step2(int inOff, int outOff, int prevOff, int dbl,
                        const float* __restrict__ W2, int k, int wr) {
    __shared__ float sW[G1C * G2C];
    __shared__ float sT[8 * 256];
    int tid = threadIdx.x;
    for (int i = tid; i < G1C * G2C; i += 256) sW[i] = W2[k * G1C * G2C + i];
    int warp = tid >> 5, lane = tid & 31;
    int node = blockIdx.x * 8 + warp;
    int beg = g_i[IO_RP2 + node], end = g_i[IO_RP2 + node + 1];
    const float4* in = (const float4*)(g_f + inOff);
    float4 a0 = make_float4(0.f, 0.f, 0.f, 0.f);
    float4 a1 = a0;
    for (int i = beg; i < end; i += 4) {
        float2 p0 = g_pk2[i];
        float2 p1 = (i + 1 < end) ? g_pk2[i + 1] : make_float2(0.f, __int_as_float(0));
        float2 p2 = (i + 2 < end) ? g_pk2[i + 2] : make_float2(0.f, __int_as_float(0));
        float2 p3 = (i + 3 < end) ? g_pk2[i + 3] : make_float2(0.f, __int_as_float(0));
        const float4* r0 = in + (size_t)__float_as_int(p0.y) * 64;
        const float4* r1 = in + (size_t)__float_as_int(p1.y) * 64;
        const float4* r2 = in + (size_t)__float_as_int(p2.y) * 64;
        const float4* r3 = in + (size_t)__float_as_int(p3.y) * 64;
        float4 v00 = r0[lane], v01 = r0[lane + 32];
        float4 v10 = r1[lane], v11 = r1[lane + 32];
        float4 v20 = r2[lane], v21 = r2[lane + 32];
        float4 v30 = r3[lane], v31 = r3[lane + 32];
        FMA4(a0, p0.x, v00); FMA4(a1, p0.x, v01);
        FMA4(a0, p1.x, v10); FMA4(a1, p1.x, v11);
        FMA4(a0, p2.x, v20); FMA4(a1, p2.x, v21);
        FMA4(a0, p3.x, v30); FMA4(a1, p3.x, v31);
    }
    if (dbl) {
        const float4* pv = (const float4*)(g_f + prevOff) + node * 64;
        float4 p0 = pv[lane], p1 = pv[lane + 32];
        a0.x = 2.f * a0.x - p0.x; a0.y = 2.f * a0.y - p0.y;
        a0.z = 2.f * a0.z - p0.z; a0.w = 2.f * a0.w - p0.w;
        a1.x = 2.f * a1.x - p1.x; a1.y = 2.f * a1.y - p1.y;
        a1.z = 2.f * a1.z - p1.z; a1.w = 2.f * a1.w - p1.w;
    }
    if (wr) {
        float4* o = (float4*)(g_f + outOff) + node * 64;
        o[lane] = a0;
        o[lane + 32] = a1;
    }
    *(float4*)&sT[warp * 256 + lane * 4] = a0;
    *(float4*)&sT[warp * 256 + 128 + lane * 4] = a1;
    __syncthreads();
    int local = tid & 127, sub = tid >> 7;
    int g = local >> 2, b = local & 3;
    int n0 = blockIdx.x * 8;
#pragma unroll
    for (int pass = 0; pass < 4; pass++) {
        int ns = pass * 2 + sub;
        float s = 0.f;
#pragma unroll
        for (int d = 0; d < G1C; d++) s = fmaf(sT[ns * 256 + d * 4 + b], sW[d * G2C + g], s);
        g_f[OFF_Y2 + (n0 + ns) * 128 + local] += s;
    }
}

// ================= B^T split conversion (relu fused) =================

__global__ void k_convBT() {
    __shared__ float s[64][65];
    int kt = blockIdx.x >> 2, nt = blockIdx.x & 3;
    int k0 = kt * 64, n0 = nt * 64;
    int t = threadIdx.x;
    {
        int r = t >> 4, c4 = t & 15;
#pragma unroll
        for (int i = 0; i < 4; i++) {
            int row = r + i * 16;
            float4 v = *(const float4*)&g_f[OFF_Y1 + (size_t)(k0 + row) * 256 + n0 + c4 * 4];
            s[row][c4 * 4 + 0] = fmaxf(v.x, 0.f);
            s[row][c4 * 4 + 1] = fmaxf(v.y, 0.f);
            s[row][c4 * 4 + 2] = fmaxf(v.z, 0.f);
            s[row][c4 * 4 + 3] = fmaxf(v.w, 0.f);
        }
    }
    __syncthreads();
    int n = t >> 2, kc = t & 3;
    unsigned short h[16], l[16];
#pragma unroll
    for (int e = 0; e < 16; e++) {
        split_bf16(s[kc * 16 + e][n], h[e], l[e]);
    }
    size_t ob = (size_t)(n0 + n) * N1 + k0 + kc * 16;
    uint4* dh = (uint4*)(g_Bthi + ob);
    uint4* dl = (uint4*)(g_Btlo + ob);
#pragma unroll
    for (int half = 0; half < 2; half++) {
        int e0 = half * 8;
        dh[half] = make_uint4((uint32_t)h[e0] | ((uint32_t)h[e0+1] << 16),
                              (uint32_t)h[e0+2] | ((uint32_t)h[e0+3] << 16),
                              (uint32_t)h[e0+4] | ((uint32_t)h[e0+5] << 16),
                              (uint32_t)h[e0+6] | ((uint32_t)h[e0+7] << 16));
        dl[half] = make_uint4((uint32_t)l[e0] | ((uint32_t)l[e0+1] << 16),
                              (uint32_t)l[e0+2] | ((uint32_t)l[e0+3] << 16),
                              (uint32_t)l[e0+4] | ((uint32_t)l[e0+5] << 16),
                              (uint32_t)l[e0+6] | ((uint32_t)l[e0+7] << 16));
    }
}

// ================= mma.sync split-bf16 GEMM (A converted inline) =================

#define SA_H 0
#define SA_L 10240
#define SB_H 20480
#define SB_L 40960
#define GSTAGE 61440
#define GSM_TOTAL (2 * GSTAGE)
#define NKCHUNK 64   // 2048 / 32

__global__ void __launch_bounds__(512, 1) k_gemm_mma(const float* __restrict__ Agl) {
    extern __shared__ char smem[];
    uint32_t sb = smem_u32(smem);
    int tid = threadIdx.x, lane = tid & 31, wid = tid >> 5;
    int mt = blockIdx.x, ks = blockIdx.y;
    int bm = mt * 128;
    int kbase = ks * 2048;

    const __nv_bfloat16* Bh = g_Bthi;
    const __nv_bfloat16* Bl = g_Btlo;

    int arow = tid >> 2, ach = tid & 3;
    int brow = tid >> 1, bch = tid & 1;
    const float* Arow = Agl + (size_t)(bm + arow) * N1 + kbase + ach * 8;

#define LOADB(kc, st) do { \
        int kb_ = kbase + (kc) * 32 + bch * 16; \
        uint32_t db_ = sb + (st) * GSTAGE + brow * 80 + bch * 32; \
        CP16(db_ + SB_H,      Bh + (size_t)brow * N1 + kb_); \
        CP16(db_ + SB_H + 16, Bh + (size_t)brow * N1 + kb_ + 8); \
        CP16(db_ + SB_L,      Bl + (size_t)brow * N1 + kb_); \
        CP16(db_ + SB_L + 16, Bl + (size_t)brow * N1 + kb_ + 8); \
    } while (0)

#define STS_A(v0, v1, st) do { \
        unsigned short h_[8], l_[8]; \
        split_bf16((v0).x, h_[0], l_[0]); split_bf16((v0).y, h_[1], l_[1]); \
        split_bf16((v0).z, h_[2], l_[2]); split_bf16((v0).w, h_[3], l_[3]); \
        split_bf16((v1).x, h_[4], l_[4]); split_bf16((v1).y, h_[5], l_[5]); \
        split_bf16((v1).z, h_[6], l_[6]); split_bf16((v1).w, h_[7], l_[7]); \
        uint32_t da_ = sb + (st) * GSTAGE + arow * 80 + ach * 16; \
        *(uint4*)(smem + (da_ - sb) + SA_H) = make_uint4( \
            (uint32_t)h_[0] | ((uint32_t)h_[1] << 16), (uint32_t)h_[2] | ((uint32_t)h_[3] << 16), \
            (uint32_t)h_[4] | ((uint32_t)h_[5] << 16), (uint32_t)h_[6] | ((uint32_t)h_[7] << 16)); \
        *(uint4*)(smem + (da_ - sb) + SA_L) = make_uint4( \
            (uint32_t)l_[0] | ((uint32_t)l_[1] << 16), (uint32_t)l_[2] | ((uint32_t)l_[3] << 16), \
            (uint32_t)l_[4] | ((uint32_t)l_[5] << 16), (uint32_t)l_[6] | ((uint32_t)l_[7] << 16)); \
    } while (0)

    {
        float4 a0 = *(const float4*)(Arow + 0 * 32);
        float4 a1 = *(const float4*)(Arow + 0 * 32 + 4);
        STS_A(a0, a1, 0);
        float4 b0 = *(const float4*)(Arow + 1 * 32);
        float4 b1 = *(const float4*)(Arow + 1 * 32 + 4);
        STS_A(b0, b1, 1);
    }
    LOADB(0, 0); CP_COMMIT();
    LOADB(1, 1); CP_COMMIT();

    int mw = wid & 3, nw = wid >> 2;
    float acc[2][8][4];
#pragma unroll
    for (int f = 0; f < 2; f++)
#pragma unroll
        for (int g = 0; g < 8; g++)
#pragma unroll
            for (int q = 0; q < 4; q++) acc[f][g][q] = 0.f;

    int qrow = lane >> 2, qk = (lane & 3) * 2;

    for (int kc = 0; kc < NKCHUNK; kc++) {
        int st = kc & 1;
        CP_WAIT1();
        __syncthreads();
        float4 pa0, pa1;
        bool pre = (kc + 2 < NKCHUNK);
        if (pre) {
            pa0 = *(const float4*)(Arow + (kc + 2) * 32);
            pa1 = *(const float4*)(Arow + (kc + 2) * 32 + 4);
        }
        uint32_t base = sb + st * GSTAGE;
#pragma unroll
        for (int kk = 0; kk < 32; kk += 16) {
            uint32_t ah[2][4], al[2][4];
#pragma unroll
            for (int f = 0; f < 2; f++) {
                uint32_t a0 = base + (mw * 32 + f * 16 + qrow) * 80 + (qk + kk) * 2;
                LDS32(ah[f][0], a0 + SA_H);
                LDS32(ah[f][1], a0 + SA_H + 8 * 80);
                LDS32(ah[f][2], a0 + SA_H + 16);
                LDS32(ah[f][3], a0 + SA_H + 8 * 80 + 16);
                LDS32(al[f][0], a0 + SA_L);
                LDS32(al[f][1], a0 + SA_L + 8 * 80);
                LDS32(al[f][2], a0 + SA_L + 16);
                LDS32(al[f][3], a0 + SA_L + 8 * 80 + 16);
            }
#pragma unroll
            for (int g = 0; g < 8; g++) {
                uint32_t bh[2], bl[2];
                uint32_t b0 = base + (nw * 64 + g * 8 + qrow) * 80 + (qk + kk) * 2;
                LDS32(bh[0], b0 + SB_H);
                LDS32(bh[1], b0 + SB_H + 16);
                LDS32(bl[0], b0 + SB_L);
                LDS32(bl[1], b0 + SB_L + 16);
#pragma unroll
                for (int f = 0; f < 2; f++) {
                    MMA_BF16(acc[f][g], ah[f], bh);
                    MMA_BF16(acc[f][g], ah[f], bl);
                    MMA_BF16(acc[f][g], al[f], bh);
                }
            }
        }
        __syncthreads();
        if (pre) {
            STS_A(pa0, pa1, st);
            LOADB(kc + 2, st);
        }
        CP_COMMIT();
    }
#undef LOADB
#undef STS_A

    float* part = g_f + OFF_PART + (size_t)ks * (N2 * 256);
#pragma unroll
    for (int f = 0; f < 2; f++) {
        int row = bm + mw * 32 + f * 16 + qrow;
#pragma unroll
        for (int g = 0; g < 8; g++) {
            int col = nw * 64 + g * 8 + (lane & 3) * 2;
            *(float2*)&part[(size_t)row * 256 + col] = make_float2(acc[f][g][0], acc[f][g][1]);
            *(float2*)&part[(size_t)(row + 8) * 256 + col] = make_float2(acc[f][g][2], acc[f][g][3]);
        }
    }
}

// ================= classifier =================

__global__ void k_fc(const float* __restrict__ fcw) {
    int blk = blockIdx.x;
    int q = blk / 48, rem = blk % 48, c = rem / 8, ks = rem % 8;
    __shared__ float red[256];
    const float4* y = (const float4*)(g_f + OFF_Y2 + (size_t)q * 131072 + ks * 16384);
    const float4* w = (const float4*)(fcw + (size_t)c * 131072 + ks * 16384);
    float s = 0.f;
#pragma unroll
    for (int it = 0; it < 16; it++) {
        int j = it * 256 + threadIdx.x;
        float4 a = y[j], b = w[j];
        s = fmaf(a.x, b.x, s); s = fmaf(a.y, b.y, s);
        s = fmaf(a.z, b.z, s); s = fmaf(a.w, b.w, s);
    }
    red[threadIdx.x] = s;
    __syncthreads();
    for (int o = 128; o > 0; o >>= 1) {
        if (threadIdx.x < o) red[threadIdx.x] += red[threadIdx.x + o];
        __syncthreads();
    }
    if (threadIdx.x == 0) g_f[OFF_FCP + blk] = red[0];
}

__global__ void k_lsm(const float* __restrict__ fcb, float* out) {
    __shared__ float logit[24];
    int t = threadIdx.x;
    if (t < 24) {
        int q = t / 6, c = t % 6;
        float s = fcb[c];
#pragma unroll
        for (int i = 0; i < 8; i++) s += g_f[OFF_FCP + q * 48 + c * 8 + i];
        logit[t] = s;
    }
    __syncwarp();
    if (t < 4) {
        float m = -1e30f;
        for (int c = 0; c < 6; c++) m = fmaxf(m, logit[t * 6 + c]);
        float se = 0.f;
        for (int c = 0; c < 6; c++) se += expf(logit[t * 6 + c] - m);
        float l = logf(se);
        for (int c = 0; c < 6; c++) out[t * 6 + c] = logit[t * 6 + c] - m - l;
    }
}

// ================= host =================

extern "C" void kernel_launch(void* const* d_in, const int* in_sizes, int n_in,
                              void* d_out, int out_size) {
    const float*     x    = (const float*)d_in[0];
    const void*      ei1  = d_in[1];
    const float*     w1e  = (const float*)d_in[2];
    const void*      ei2  = d_in[3];
    const float*     w2e  = (const float*)d_in[4];
    const float*     bmap = (const float*)d_in[5];
    const float*     W1   = (const float*)d_in[6];
    const float*     bias1= (const float*)d_in[7];
    const float*     W2   = (const float*)d_in[8];
    const float*     bias2= (const float*)d_in[9];
    const float*     fcw  = (const float*)d_in[10];
    const float*     fcb  = (const float*)d_in[11];
    float*           out  = (float*)d_out;
    (void)in_sizes; (void)n_in; (void)out_size;

    cudaFuncSetAttribute(k_gemm_mma, cudaFuncAttributeMaxDynamicSharedMemorySize, GSM_TOTAL);

    // --- preprocessing (6 launches) ---
    k_init<<<(E1C + 255) / 256, 256>>>((const long long*)ei1);
    k_decode_count<<<(E1C + E2C + 255) / 256, 256>>>(ei1, ei2);
    k_scan2<<<2, 1024>>>();
    k_fill2<<<(E1C + E2C + 255) / 256, 256>>>();
    k_sortdeg<<<(N1 + N2 + 127) / 128, 128>>>(w1e, w2e);
    k_pack_norm<<<(E1C + E2C + 255) / 256, 256>>>(w1e, w2e);

    // --- conv1: xpose -> 11 gather-only props -> one hoisted einsum ---
    k_xpose<<<N1 / 8, 256>>>(x);
    for (int k = 1; k < KCH; k++) {
        int in = OFF_T1 + (k - 1) * T1_STRIDE;
        int o  = OFF_T1 + k * T1_STRIDE;
        int pv = OFF_T1 + (k - 2) * T1_STRIDE;  // unused when k==1
        k_prop1<<<N1 / 8, 256>>>(in, o, (k >= 2) ? pv : OFF_T1, (k >= 2) ? 1 : 0);
    }
    k_ein1_all<<<N1 / 8, 256>>>(W1, bias1);

    // --- split-bf16 mma GEMM (A converted inline; relu fused into convBT) ---
    k_convBT<<<512, 256>>>();
    dim3 gg(32, 4);
    k_gemm_mma<<<gg, 512, GSM_TOTAL>>>(bmap);

    // --- conv2: reduce+ein0, then 11 fused prop+ein steps (unchanged) ---
    int b2buf[3] = {OFF_T2, OFF_T2 + T2_STRIDE, OFF_T2 + 2 * T2_STRIDE};
    k_red_ein0<<<N2 / 8, 256>>>(W2, bias2);
    k_step2<<<N2 / 8, 256>>>(b2buf[0], b2buf[1], 0, 0, W2, 1, 1);
    for (int k = 2; k < KCH; k++) {
        int in = b2buf[(k - 1) % 3], o = b2buf[k % 3], pv = b2buf[(k - 2) % 3];
        k_step2<<<N2 / 8, 256>>>(in, o, pv, 1, W2, k, (k < KCH - 1) ? 1 : 0);
    }

    // --- fc + log_softmax ---
    k_fc<<<192, 256>>>(fcw);
    k_lsm<<<1, 32>>>(fcb, out);
}

// round 16
// speedup vs baseline: 1.0835x; 1.0331x over previous
#include <cuda_runtime.h>
#include <cuda_bf16.h>
#include <cstdint>
#include <stdint.h>
#include <math.h>

// ---------------- problem constants ----------------
#define N1   8192
#define N2   4096
#define TT   15
#define BS   4
#define E1C  131072
#define E2C  65536
#define KCH  12
#define G1C  64
#define G2C  32
#define NC   6

// ---------------- float scratch layout ----------------
#define T1_STRIDE (N1*64)
#define OFF_T1    0
// 12 T1 buffers (slot 11 unused now; layout kept stable)
#define OFF_Y1    (OFF_T1 + 12*T1_STRIDE)
#define T2_STRIDE (N2*256)
#define OFF_T2    (OFF_Y1 + N1*256)
#define OFF_Y2    (OFF_T2 + 3*T2_STRIDE)
#define OFF_DEG1  (OFF_Y2 + N2*128)
#define OFF_DEG2  (OFF_DEG1 + N1)
#define OFF_LOG   (OFF_DEG2 + N2)
#define OFF_FCP   (OFF_LOG + 64)
#define OFF_PART  (OFF_FCP + 256)
#define SCRATCH_F (OFF_PART + 4*N2*256)

__device__ __align__(16) float g_f[SCRATCH_F];

// bf16 split buffers for B^T only (A converted inline in the GEMM)
__device__ __align__(16) __nv_bfloat16 g_Bthi[(size_t)256 * N1]; // B^T: [256][8192]
__device__ __align__(16) __nv_bfloat16 g_Btlo[(size_t)256 * N1];

// packed CSR edge data: (norm, src-as-float-bits) in CSR position order
__device__ __align__(16) float2 g_pk1[E1C];
__device__ __align__(16) float2 g_pk2[E2C];

// int64-vs-int32 edge dtype flag: OR-only, converges after first call, replay-stable
__device__ int g_flag = 0;

// ---------------- int scratch layout ----------------
#define IO_RP1   1
#define IO_CU1   (IO_RP1 + N1 + 1)
#define IO_EI1   (IO_CU1 + N1)
#define IO_SRC1  (IO_EI1 + E1C)
#define IO_DST1  (IO_SRC1 + E1C)
#define IO_RP2   (IO_DST1 + E1C)
#define IO_CU2   (IO_RP2 + N2 + 1)
#define IO_EI2   (IO_CU2 + N2)
#define IO_SRC2  (IO_EI2 + E2C)
#define IO_DST2  (IO_SRC2 + E2C)
#define SCRATCH_I (IO_DST2 + E2C)

__device__ int g_i[SCRATCH_I];

// ================= helpers =================

__device__ __forceinline__ uint32_t smem_u32(const void* p) {
    uint32_t a;
    asm("{ .reg .u64 t; cvta.to.shared.u64 t, %1; cvt.u32.u64 %0, t; }" : "=r"(a) : "l"(p));
    return a;
}

#define CP16(dst, src) \
    asm volatile("cp.async.cg.shared.global [%0], [%1], 16;" :: "r"(dst), "l"(src))
#define CP_COMMIT() asm volatile("cp.async.commit_group;" ::: "memory")
#define CP_WAIT1()  asm volatile("cp.async.wait_group 1;" ::: "memory")

#define LDS32(v, a) asm volatile("ld.shared.b32 %0, [%1];" : "=r"(v) : "r"(a))

#define MMA_BF16(c, a, b) \
    asm volatile("mma.sync.aligned.m16n8k16.row.col.f32.bf16.bf16.f32 " \
        "{%0,%1,%2,%3}, {%4,%5,%6,%7}, {%8,%9}, {%0,%1,%2,%3};" \
        : "+f"((c)[0]), "+f"((c)[1]), "+f"((c)[2]), "+f"((c)[3]) \
        : "r"((a)[0]), "r"((a)[1]), "r"((a)[2]), "r"((a)[3]), \
          "r"((b)[0]), "r"((b)[1]))

#define FMA4(acc, nm, v) do { \
    (acc).x = fmaf((nm), (v).x, (acc).x); \
    (acc).y = fmaf((nm), (v).y, (acc).y); \
    (acc).z = fmaf((nm), (v).z, (acc).z); \
    (acc).w = fmaf((nm), (v).w, (acc).w); } while (0)

__device__ __forceinline__ void split_bf16(float v, unsigned short& h, unsigned short& l) {
    h = __bfloat16_as_ushort(__float2bfloat16(v));
    float r = v - __bfloat162float(__ushort_as_bfloat16(h));
    l = __bfloat16_as_ushort(__float2bfloat16(r));
}

// ================= preprocessing (fused, 6 launches) =================

__global__ void k_init(const long long* p) {
    int i = blockIdx.x * blockDim.x + threadIdx.x;
    if (i < N1) g_i[IO_CU1 + i] = 0;
    if (i < N2) g_i[IO_CU2 + i] = 0;
    if (i < E1C) {
        long long v = p[i];
        if (v < 0 || v >= (long long)N1) atomicOr(&g_flag, 1);
    }
}

__global__ void k_decode_count(const void* ei1, const void* ei2) {
    int e = blockIdx.x * blockDim.x + threadIdx.x;
    int is32 = g_flag;
    const void* eiv; int E, srcOff, dstOff, cuOff, le;
    if (e < E1C) { eiv = ei1; E = E1C; srcOff = IO_SRC1; dstOff = IO_DST1; cuOff = IO_CU1; le = e; }
    else if (e < E1C + E2C) { eiv = ei2; E = E2C; srcOff = IO_SRC2; dstOff = IO_DST2; cuOff = IO_CU2; le = e - E1C; }
    else return;
    int s, d;
    if (is32) {
        const int* p = (const int*)eiv;
        s = p[le]; d = p[E + le];
    } else {
        const long long* p = (const long long*)eiv;
        s = (int)p[le]; d = (int)p[E + le];
    }
    g_i[srcOff + le] = s;
    g_i[dstOff + le] = d;
    atomicAdd(&g_i[cuOff + d], 1);
}

__global__ void k_scan2() {
    __shared__ int part[1024];
    int n, cntOff, rpOff;
    if (blockIdx.x == 0) { n = N1; cntOff = IO_CU1; rpOff = IO_RP1; }
    else                 { n = N2; cntOff = IO_CU2; rpOff = IO_RP2; }
    int t = threadIdx.x;
    int chunk = (n + 1023) >> 10;
    int base = t * chunk;
    int s = 0;
    for (int i = 0; i < chunk; i++) { int idx = base + i; if (idx < n) s += g_i[cntOff + idx]; }
    part[t] = s;
    __syncthreads();
    for (int off = 1; off < 1024; off <<= 1) {
        int v = (t >= off) ? part[t - off] : 0;
        __syncthreads();
        part[t] += v;
        __syncthreads();
    }
    int run = (t > 0) ? part[t - 1] : 0;
    for (int i = 0; i < chunk; i++) {
        int idx = base + i;
        if (idx < n) {
            int v = g_i[cntOff + idx];
            g_i[rpOff + idx] = run;
            g_i[cntOff + idx] = run;
            run += v;
        }
    }
    if (t == 1023) g_i[rpOff + n] = part[1023];
}

__global__ void k_fill2() {
    int e = blockIdx.x * blockDim.x + threadIdx.x;
    if (e < E1C) {
        int d = g_i[IO_DST1 + e];
        int p = atomicAdd(&g_i[IO_CU1 + d], 1);
        g_i[IO_EI1 + p] = e;
    } else if (e < E1C + E2C) {
        int le = e - E1C;
        int d = g_i[IO_DST2 + le];
        int p = atomicAdd(&g_i[IO_CU2 + d], 1);
        g_i[IO_EI2 + p] = le;
    }
}

__global__ void k_sortdeg(const float* w1, const float* w2) {
    int idx = blockIdx.x * blockDim.x + threadIdx.x;
    int rpOff, eidOff, degOff, node;
    const float* w;
    if (idx < N1) { node = idx; rpOff = IO_RP1; eidOff = IO_EI1; degOff = OFF_DEG1; w = w1; }
    else if (idx < N1 + N2) { node = idx - N1; rpOff = IO_RP2; eidOff = IO_EI2; degOff = OFF_DEG2; w = w2; }
    else return;
    int beg = g_i[rpOff + node], end = g_i[rpOff + node + 1];
    for (int i = beg + 1; i < end; i++) {
        int key = g_i[eidOff + i];
        int j = i - 1;
        while (j >= beg && g_i[eidOff + j] > key) {
            g_i[eidOff + j + 1] = g_i[eidOff + j];
            j--;
        }
        g_i[eidOff + j + 1] = key;
    }
    float s = 0.f;
    for (int i = beg; i < end; i++) s += w[g_i[eidOff + i]];
    g_f[degOff + node] = s;
}

__global__ void k_pack_norm(const float* w1, const float* w2) {
    int p = blockIdx.x * blockDim.x + threadIdx.x;
    if (p < E1C) {
        int e = g_i[IO_EI1 + p];
        int s = g_i[IO_SRC1 + e], d = g_i[IO_DST1 + e];
        float ds = g_f[OFF_DEG1 + s];
        float dd = g_f[OFF_DEG1 + d];
        float rs = (ds > 0.f) ? rsqrtf(ds) : 0.f;
        float rd = (dd > 0.f) ? rsqrtf(dd) : 0.f;
        g_pk1[p] = make_float2(-w1[e] * rs * rd, __int_as_float(s));
    } else if (p < E1C + E2C) {
        int lp = p - E1C;
        int e = g_i[IO_EI2 + lp];
        int s = g_i[IO_SRC2 + e], d = g_i[IO_DST2 + e];
        float ds = g_f[OFF_DEG2 + s];
        float dd = g_f[OFF_DEG2 + d];
        float rs = (ds > 0.f) ? rsqrtf(ds) : 0.f;
        float rd = (dd > 0.f) ? rsqrtf(dd) : 0.f;
        g_pk2[lp] = make_float2(-w2[e] * rs * rd, __int_as_float(s));
    }
}

// ================= conv1: gather-only props + fused final-step einsum+BT =================

// x (B,N1,T) -> T1[0] (N1, 64), j = d*4+b, d>=15 zero-padded
__global__ void k_xpose(const float* __restrict__ x) {
    int tid = threadIdx.x;
    int n0 = blockIdx.x * 8;
#pragma unroll
    for (int it = 0; it < 2; it++) {
        int i = it * 256 + tid;
        int ns = i >> 6, j = i & 63;
        int d = j >> 2, b = j & 3;
        float v = (d < TT) ? x[(size_t)b * (N1 * TT) + (n0 + ns) * TT + d] : 0.f;
        g_f[OFF_T1 + (n0 + ns) * 64 + j] = v;
    }
}

// gather-only Chebyshev step for conv1 (proven R15 body)
__global__ void k_prop1(int inOff, int outOff, int prevOff, int dbl) {
    int tid = threadIdx.x;
    int warp = tid >> 5, lane = tid & 31;
    int node = blockIdx.x * 8 + warp;
    int half = lane >> 4, c4 = lane & 15;
    int beg = g_i[IO_RP1 + node], end = g_i[IO_RP1 + node + 1];
    const float4* in = (const float4*)(g_f + inOff);
    float4 acc = make_float4(0.f, 0.f, 0.f, 0.f);
    for (int i = beg + half; i < end; i += 8) {
        float2 p0 = g_pk1[i];
        float2 p1 = (i + 2 < end) ? g_pk1[i + 2] : make_float2(0.f, __int_as_float(0));
        float2 p2 = (i + 4 < end) ? g_pk1[i + 4] : make_float2(0.f, __int_as_float(0));
        float2 p3 = (i + 6 < end) ? g_pk1[i + 6] : make_float2(0.f, __int_as_float(0));
        float4 v0 = in[__float_as_int(p0.y) * 16 + c4];
        float4 v1 = in[__float_as_int(p1.y) * 16 + c4];
        float4 v2 = in[__float_as_int(p2.y) * 16 + c4];
        float4 v3 = in[__float_as_int(p3.y) * 16 + c4];
        FMA4(acc, p0.x, v0);
        FMA4(acc, p1.x, v1);
        FMA4(acc, p2.x, v2);
        FMA4(acc, p3.x, v3);
    }
    acc.x += __shfl_down_sync(0xffffffffu, acc.x, 16);
    acc.y += __shfl_down_sync(0xffffffffu, acc.y, 16);
    acc.z += __shfl_down_sync(0xffffffffu, acc.z, 16);
    acc.w += __shfl_down_sync(0xffffffffu, acc.w, 16);
    if (half == 0) {
        float4 r = acc;
        if (dbl) {
            float4 p = ((const float4*)(g_f + prevOff))[node * 16 + c4];
            r.x = 2.f * r.x - p.x;
            r.y = 2.f * r.y - p.y;
            r.z = 2.f * r.z - p.z;
            r.w = 2.f * r.w - p.w;
        }
        ((float4*)(g_f + outOff))[node * 16 + c4] = r;
    }
}

// Fused: T11 gather (in smem only) + hoisted einsum over k=0..11 + relu + split-bf16
// + transposed write to B^T hi/lo. Y1 and T1[11] never touch global memory.
__global__ void k_ein1_bt(const float* __restrict__ W1, const float* __restrict__ bias1) {
    __shared__ float sW[TT * G1C];
    __shared__ float sT[8 * 64];
    __shared__ float sT11[8 * 64];
    int tid = threadIdx.x;
    int n0 = blockIdx.x * 8;
    int warp = tid >> 5, lane = tid & 31;
    int half = lane >> 4, c4 = lane & 15;

    // --- gather T11 = 2 L T10 - T9 for own nodes (proven R14 k_step1 front half) ---
    {
        int node = n0 + warp;
        int beg = g_i[IO_RP1 + node], end = g_i[IO_RP1 + node + 1];
        const float4* in = (const float4*)(g_f + OFF_T1 + 10 * T1_STRIDE);
        float4 acc = make_float4(0.f, 0.f, 0.f, 0.f);
        for (int i = beg + half; i < end; i += 8) {
            float2 p0 = g_pk1[i];
            float2 p1 = (i + 2 < end) ? g_pk1[i + 2] : make_float2(0.f, __int_as_float(0));
            float2 p2 = (i + 4 < end) ? g_pk1[i + 4] : make_float2(0.f, __int_as_float(0));
            float2 p3 = (i + 6 < end) ? g_pk1[i + 6] : make_float2(0.f, __int_as_float(0));
            float4 v0 = in[__float_as_int(p0.y) * 16 + c4];
            float4 v1 = in[__float_as_int(p1.y) * 16 + c4];
            float4 v2 = in[__float_as_int(p2.y) * 16 + c4];
            float4 v3 = in[__float_as_int(p3.y) * 16 + c4];
            FMA4(acc, p0.x, v0);
            FMA4(acc, p1.x, v1);
            FMA4(acc, p2.x, v2);
            FMA4(acc, p3.x, v3);
        }
        acc.x += __shfl_down_sync(0xffffffffu, acc.x, 16);
        acc.y += __shfl_down_sync(0xffffffffu, acc.y, 16);
        acc.z += __shfl_down_sync(0xffffffffu, acc.z, 16);
        acc.w += __shfl_down_sync(0xffffffffu, acc.w, 16);
        if (half == 0) {
            float4 p = ((const float4*)(g_f + OFF_T1 + 9 * T1_STRIDE))[node * 16 + c4];
            float4 r;
            r.x = 2.f * acc.x - p.x;
            r.y = 2.f * acc.y - p.y;
            r.z = 2.f * acc.z - p.z;
            r.w = 2.f * acc.w - p.w;
            *(float4*)&sT11[warp * 64 + c4 * 4] = r;
        }
    }

    // --- hoisted einsum: y = bias + sum_{k=0..10} T1[k].W1[k] + T11.W1[11] ---
    int g = tid >> 2, b = tid & 3;
    float y[8];
    float bv = bias1[g];
#pragma unroll
    for (int ns = 0; ns < 8; ns++) y[ns] = bv;
    for (int k = 0; k < KCH - 1; k++) {
        __syncthreads();
        for (int i = tid; i < TT * G1C; i += 256) sW[i] = W1[k * TT * G1C + i];
        sT[tid]       = g_f[OFF_T1 + k * T1_STRIDE + n0 * 64 + tid];
        sT[tid + 256] = g_f[OFF_T1 + k * T1_STRIDE + n0 * 64 + tid + 256];
        __syncthreads();
#pragma unroll
        for (int ns = 0; ns < 8; ns++) {
            float s = 0.f;
#pragma unroll
            for (int d = 0; d < TT; d++) s = fmaf(sT[ns * 64 + d * 4 + b], sW[d * G1C + g], s);
            y[ns] += s;
        }
    }
    // k = 11 from sT11
    __syncthreads();
    for (int i = tid; i < TT * G1C; i += 256) sW[i] = W1[(KCH - 1) * TT * G1C + i];
    __syncthreads();
#pragma unroll
    for (int ns = 0; ns < 8; ns++) {
        float s = 0.f;
#pragma unroll
        for (int d = 0; d < TT; d++) s = fmaf(sT11[ns * 64 + d * 4 + b], sW[d * G1C + g], s);
        y[ns] += s;
    }

    // --- relu + split-bf16 + transposed write: B^T row j=tid, cols n0..n0+7 ---
    unsigned short h[8], l[8];
#pragma unroll
    for (int ns = 0; ns < 8; ns++) {
        float v = fmaxf(y[ns], 0.f);
        split_bf16(v, h[ns], l[ns]);
    }
    uint4 uh = make_uint4((uint32_t)h[0] | ((uint32_t)h[1] << 16),
                          (uint32_t)h[2] | ((uint32_t)h[3] << 16),
                          (uint32_t)h[4] | ((uint32_t)h[5] << 16),
                          (uint32_t)h[6] | ((uint32_t)h[7] << 16));
    uint4 ul = make_uint4((uint32_t)l[0] | ((uint32_t)l[1] << 16),
                          (uint32_t)l[2] | ((uint32_t)l[3] << 16),
                          (uint32_t)l[4] | ((uint32_t)l[5] << 16),
                          (uint32_t)l[6] | ((uint32_t)l[7] << 16));
    *(uint4*)(g_Bthi + (size_t)tid * N1 + n0) = uh;
    *(uint4*)(g_Btlo + (size_t)tid * N1 + n0) = ul;
}

// ================= conv2: fused kernels (exact R14/R15 bodies) =================

__global__ void k_red_ein0(const float* __restrict__ W2, const float* __restrict__ bias2) {
    __shared__ float sW[G1C * G2C];
    __shared__ float sT[8 * 256];
    int tid = threadIdx.x;
    int n0 = blockIdx.x * 8;
    for (int i = tid; i < G1C * G2C; i += 256) sW[i] = W2[i];
#pragma unroll
    for (int ns = 0; ns < 8; ns++) {
        size_t gi = (size_t)(n0 + ns) * 256 + tid;
        float v = g_f[OFF_PART + gi] + g_f[OFF_PART + (N2 * 256) + gi]
                + g_f[OFF_PART + 2 * (N2 * 256) + gi] + g_f[OFF_PART + 3 * (N2 * 256) + gi];
        g_f[OFF_T2 + gi] = v;
        sT[ns * 256 + tid] = v;
    }
    __syncthreads();
    int local = tid & 127, sub = tid >> 7;
    int g = local >> 2, b = local & 3;
    float bv = bias2[g];
#pragma unroll
    for (int pass = 0; pass < 4; pass++) {
        int ns = pass * 2 + sub;
        float s = 0.f;
#pragma unroll
        for (int d = 0; d < G1C; d++) s = fmaf(sT[ns * 256 + d * 4 + b], sW[d * G2C + g], s);
        g_f[OFF_Y2 + (n0 + ns) * 128 + local] = s + bv;
    }
}

__global__ void k_step2(int inOff, int outOff, int prevOff, int dbl,
                        const float* __restrict__ W2, int k, int wr) {
    __shared__ float sW[G1C * G2C];
    __shared__ float sT[8 * 256];
    int tid = threadIdx.x;
    for (int i = tid; i < G1C * G2C; i += 256) sW[i] = W2[k * G1C * G2C + i];
    int warp = tid >> 5, lane = tid & 31;
    int node = blockIdx.x * 8 + warp;
    int beg = g_i[IO_RP2 + node], end = g_i[IO_RP2 + node + 1];
    const float4* in = (const float4*)(g_f + inOff);
    float4 a0 = make_float4(0.f, 0.f, 0.f, 0.f);
    float4 a1 = a0;
    for (int i = beg; i < end; i += 4) {
        float2 p0 = g_pk2[i];
        float2 p1 = (i + 1 < end) ? g_pk2[i + 1] : make_float2(0.f, __int_as_float(0));
        float2 p2 = (i + 2 < end) ? g_pk2[i + 2] : make_float2(0.f, __int_as_float(0));
        float2 p3 = (i + 3 < end) ? g_pk2[i + 3] : make_float2(0.f, __int_as_float(0));
        const float4* r0 = in + (size_t)__float_as_int(p0.y) * 64;
        const float4* r1 = in + (size_t)__float_as_int(p1.y) * 64;
        const float4* r2 = in + (size_t)__float_as_int(p2.y) * 64;
        const float4* r3 = in + (size_t)__float_as_int(p3.y) * 64;
        float4 v00 = r0[lane], v01 = r0[lane + 32];
        float4 v10 = r1[lane], v11 = r1[lane + 32];
        float4 v20 = r2[lane], v21 = r2[lane + 32];
        float4 v30 = r3[lane], v31 = r3[lane + 32];
        FMA4(a0, p0.x, v00); FMA4(a1, p0.x, v01);
        FMA4(a0, p1.x, v10); FMA4(a1, p1.x, v11);
        FMA4(a0, p2.x, v20); FMA4(a1, p2.x, v21);
        FMA4(a0, p3.x, v30); FMA4(a1, p3.x, v31);
    }
    if (dbl) {
        const float4* pv = (const float4*)(g_f + prevOff) + node * 64;
        float4 p0 = pv[lane], p1 = pv[lane + 32];
        a0.x = 2.f * a0.x - p0.x; a0.y = 2.f * a0.y - p0.y;
        a0.z = 2.f * a0.z - p0.z; a0.w = 2.f * a0.w - p0.w;
        a1.x = 2.f * a1.x - p1.x; a1.y = 2.f * a1.y - p1.y;
        a1.z = 2.f * a1.z - p1.z; a1.w = 2.f * a1.w - p1.w;
    }
    if (wr) {
        float4* o = (float4*)(g_f + outOff) + node * 64;
        o[lane] = a0;
        o[lane + 32] = a1;
    }
    *(float4*)&sT[warp * 256 + lane * 4] = a0;
    *(float4*)&sT[warp * 256 + 128 + lane * 4] = a1;
    __syncthreads();
    int local = tid & 127, sub = tid >> 7;
    int g = local >> 2, b = local & 3;
    int n0 = blockIdx.x * 8;
#pragma unroll
    for (int pass = 0; pass < 4; pass++) {
        int ns = pass * 2 + sub;
        float s = 0.f;
#pragma unroll
        for (int d = 0; d < G1C; d++) s = fmaf(sT[ns * 256 + d * 4 + b], sW[d * G2C + g], s);
        g_f[OFF_Y2 + (n0 + ns) * 128 + local] += s;
    }
}

// ================= mma.sync split-bf16 GEMM (A converted inline) =================

#define SA_H 0
#define SA_L 10240
#define SB_H 20480
#define SB_L 40960
#define GSTAGE 61440
#define GSM_TOTAL (2 * GSTAGE)
#define NKCHUNK 64   // 2048 / 32

__global__ void __launch_bounds__(512, 1) k_gemm_mma(const float* __restrict__ Agl) {
    extern __shared__ char smem[];
    uint32_t sb = smem_u32(smem);
    int tid = threadIdx.x, lane = tid & 31, wid = tid >> 5;
    int mt = blockIdx.x, ks = blockIdx.y;
    int bm = mt * 128;
    int kbase = ks * 2048;

    const __nv_bfloat16* Bh = g_Bthi;
    const __nv_bfloat16* Bl = g_Btlo;

    int arow = tid >> 2, ach = tid & 3;
    int brow = tid >> 1, bch = tid & 1;
    const float* Arow = Agl + (size_t)(bm + arow) * N1 + kbase + ach * 8;

#define LOADB(kc, st) do { \
        int kb_ = kbase + (kc) * 32 + bch * 16; \
        uint32_t db_ = sb + (st) * GSTAGE + brow * 80 + bch * 32; \
        CP16(db_ + SB_H,      Bh + (size_t)brow * N1 + kb_); \
        CP16(db_ + SB_H + 16, Bh + (size_t)brow * N1 + kb_ + 8); \
        CP16(db_ + SB_L,      Bl + (size_t)brow * N1 + kb_); \
        CP16(db_ + SB_L + 16, Bl + (size_t)brow * N1 + kb_ + 8); \
    } while (0)

#define STS_A(v0, v1, st) do { \
        unsigned short h_[8], l_[8]; \
        split_bf16((v0).x, h_[0], l_[0]); split_bf16((v0).y, h_[1], l_[1]); \
        split_bf16((v0).z, h_[2], l_[2]); split_bf16((v0).w, h_[3], l_[3]); \
        split_bf16((v1).x, h_[4], l_[4]); split_bf16((v1).y, h_[5], l_[5]); \
        split_bf16((v1).z, h_[6], l_[6]); split_bf16((v1).w, h_[7], l_[7]); \
        uint32_t da_ = sb + (st) * GSTAGE + arow * 80 + ach * 16; \
        *(uint4*)(smem + (da_ - sb) + SA_H) = make_uint4( \
            (uint32_t)h_[0] | ((uint32_t)h_[1] << 16), (uint32_t)h_[2] | ((uint32_t)h_[3] << 16), \
            (uint32_t)h_[4] | ((uint32_t)h_[5] << 16), (uint32_t)h_[6] | ((uint32_t)h_[7] << 16)); \
        *(uint4*)(smem + (da_ - sb) + SA_L) = make_uint4( \
            (uint32_t)l_[0] | ((uint32_t)l_[1] << 16), (uint32_t)l_[2] | ((uint32_t)l_[3] << 16), \
            (uint32_t)l_[4] | ((uint32_t)l_[5] << 16), (uint32_t)l_[6] | ((uint32_t)l_[7] << 16)); \
    } while (0)

    {
        float4 a0 = *(const float4*)(Arow + 0 * 32);
        float4 a1 = *(const float4*)(Arow + 0 * 32 + 4);
        STS_A(a0, a1, 0);
        float4 b0 = *(const float4*)(Arow + 1 * 32);
        float4 b1 = *(const float4*)(Arow + 1 * 32 + 4);
        STS_A(b0, b1, 1);
    }
    LOADB(0, 0); CP_COMMIT();
    LOADB(1, 1); CP_COMMIT();

    int mw = wid & 3, nw = wid >> 2;
    float acc[2][8][4];
#pragma unroll
    for (int f = 0; f < 2; f++)
#pragma unroll
        for (int g = 0; g < 8; g++)
#pragma unroll
            for (int q = 0; q < 4; q++) acc[f][g][q] = 0.f;

    int qrow = lane >> 2, qk = (lane & 3) * 2;

    for (int kc = 0; kc < NKCHUNK; kc++) {
        int st = kc & 1;
        CP_WAIT1();
        __syncthreads();
        float4 pa0, pa1;
        bool pre = (kc + 2 < NKCHUNK);
        if (pre) {
            pa0 = *(const float4*)(Arow + (kc + 2) * 32);
            pa1 = *(const float4*)(Arow + (kc + 2) * 32 + 4);
        }
        uint32_t base = sb + st * GSTAGE;
#pragma unroll
        for (int kk = 0; kk < 32; kk += 16) {
            uint32_t ah[2][4], al[2][4];
#pragma unroll
            for (int f = 0; f < 2; f++) {
                uint32_t a0 = base + (mw * 32 + f * 16 + qrow) * 80 + (qk + kk) * 2;
                LDS32(ah[f][0], a0 + SA_H);
                LDS32(ah[f][1], a0 + SA_H + 8 * 80);
                LDS32(ah[f][2], a0 + SA_H + 16);
                LDS32(ah[f][3], a0 + SA_H + 8 * 80 + 16);
                LDS32(al[f][0], a0 + SA_L);
                LDS32(al[f][1], a0 + SA_L + 8 * 80);
                LDS32(al[f][2], a0 + SA_L + 16);
                LDS32(al[f][3], a0 + SA_L + 8 * 80 + 16);
            }
#pragma unroll
            for (int g = 0; g < 8; g++) {
                uint32_t bh[2], bl[2];
                uint32_t b0 = base + (nw * 64 + g * 8 + qrow) * 80 + (qk + kk) * 2;
                LDS32(bh[0], b0 + SB_H);
                LDS32(bh[1], b0 + SB_H + 16);
                LDS32(bl[0], b0 + SB_L);
                LDS32(bl[1], b0 + SB_L + 16);
#pragma unroll
                for (int f = 0; f < 2; f++) {
                    MMA_BF16(acc[f][g], ah[f], bh);
                    MMA_BF16(acc[f][g], ah[f], bl);
                    MMA_BF16(acc[f][g], al[f], bh);
                }
            }
        }
        __syncthreads();
        if (pre) {
            STS_A(pa0, pa1, st);
            LOADB(kc + 2, st);
        }
        CP_COMMIT();
    }
#undef LOADB
#undef STS_A

    float* part = g_f + OFF_PART + (size_t)ks * (N2 * 256);
#pragma unroll
    for (int f = 0; f < 2; f++) {
        int row = bm + mw * 32 + f * 16 + qrow;
#pragma unroll
        for (int g = 0; g < 8; g++) {
            int col = nw * 64 + g * 8 + (lane & 3) * 2;
            *(float2*)&part[(size_t)row * 256 + col] = make_float2(acc[f][g][0], acc[f][g][1]);
            *(float2*)&part[(size_t)(row + 8) * 256 + col] = make_float2(acc[f][g][2], acc[f][g][3]);
        }
    }
}

// ================= classifier =================

__global__ void k_fc(const float* __restrict__ fcw) {
    int blk = blockIdx.x;
    int q = blk / 48, rem = blk % 48, c = rem / 8, ks = rem % 8;
    __shared__ float red[256];
    const float4* y = (const float4*)(g_f + OFF_Y2 + (size_t)q * 131072 + ks * 16384);
    const float4* w = (const float4*)(fcw + (size_t)c * 131072 + ks * 16384);
    float s = 0.f;
#pragma unroll
    for (int it = 0; it < 16; it++) {
        int j = it * 256 + threadIdx.x;
        float4 a = y[j], b = w[j];
        s = fmaf(a.x, b.x, s); s = fmaf(a.y, b.y, s);
        s = fmaf(a.z, b.z, s); s = fmaf(a.w, b.w, s);
    }
    red[threadIdx.x] = s;
    __syncthreads();
    for (int o = 128; o > 0; o >>= 1) {
        if (threadIdx.x < o) red[threadIdx.x] += red[threadIdx.x + o];
        __syncthreads();
    }
    if (threadIdx.x == 0) g_f[OFF_FCP + blk] = red[0];
}

__global__ void k_lsm(const float* __restrict__ fcb, float* out) {
    __shared__ float logit[24];
    int t = threadIdx.x;
    if (t < 24) {
        int q = t / 6, c = t % 6;
        float s = fcb[c];
#pragma unroll
        for (int i = 0; i < 8; i++) s += g_f[OFF_FCP + q * 48 + c * 8 + i];
        logit[t] = s;
    }
    __syncwarp();
    if (t < 4) {
        float m = -1e30f;
        for (int c = 0; c < 6; c++) m = fmaxf(m, logit[t * 6 + c]);
        float se = 0.f;
        for (int c = 0; c < 6; c++) se += expf(logit[t * 6 + c] - m);
        float l = logf(se);
        for (int c = 0; c < 6; c++) out[t * 6 + c] = logit[t * 6 + c] - m - l;
    }
}

// ================= host =================

extern "C" void kernel_launch(void* const* d_in, const int* in_sizes, int n_in,
                              void* d_out, int out_size) {
    const float*     x    = (const float*)d_in[0];
    const void*      ei1  = d_in[1];
    const float*     w1e  = (const float*)d_in[2];
    const void*      ei2  = d_in[3];
    const float*     w2e  = (const float*)d_in[4];
    const float*     bmap = (const float*)d_in[5];
    const float*     W1   = (const float*)d_in[6];
    const float*     bias1= (const float*)d_in[7];
    const float*     W2   = (const float*)d_in[8];
    const float*     bias2= (const float*)d_in[9];
    const float*     fcw  = (const float*)d_in[10];
    const float*     fcb  = (const float*)d_in[11];
    float*           out  = (float*)d_out;
    (void)in_sizes; (void)n_in; (void)out_size;

    cudaFuncSetAttribute(k_gemm_mma, cudaFuncAttributeMaxDynamicSharedMemorySize, GSM_TOTAL);

    // --- preprocessing (6 launches) ---
    k_init<<<(E1C + 255) / 256, 256>>>((const long long*)ei1);
    k_decode_count<<<(E1C + E2C + 255) / 256, 256>>>(ei1, ei2);
    k_scan2<<<2, 1024>>>();
    k_fill2<<<(E1C + E2C + 255) / 256, 256>>>();
    k_sortdeg<<<(N1 + N2 + 127) / 128, 128>>>(w1e, w2e);
    k_pack_norm<<<(E1C + E2C + 255) / 256, 256>>>(w1e, w2e);

    // --- conv1: xpose -> 10 gather-only props (k=1..10) -> fused T11+einsum+relu+BT ---
    k_xpose<<<N1 / 8, 256>>>(x);
    for (int k = 1; k <= 10; k++) {
        int in = OFF_T1 + (k - 1) * T1_STRIDE;
        int o  = OFF_T1 + k * T1_STRIDE;
        int pv = OFF_T1 + (k - 2) * T1_STRIDE;  // unused when k==1
        k_prop1<<<N1 / 8, 256>>>(in, o, (k >= 2) ? pv : OFF_T1, (k >= 2) ? 1 : 0);
    }
    k_ein1_bt<<<N1 / 8, 256>>>(W1, bias1);

    // --- split-bf16 mma GEMM (A converted inline; B^T produced by k_ein1_bt) ---
    dim3 gg(32, 4);
    k_gemm_mma<<<gg, 512, GSM_TOTAL>>>(bmap);

    // --- conv2: reduce+ein0, then 11 fused prop+ein steps (unchanged) ---
    int b2buf[3] = {OFF_T2, OFF_T2 + T2_STRIDE, OFF_T2 + 2 * T2_STRIDE};
    k_red_ein0<<<N2 / 8, 256>>>(W2, bias2);
    k_step2<<<N2 / 8, 256>>>(b2buf[0], b2buf[1], 0, 0, W2, 1, 1);
    for (int k = 2; k < KCH; k++) {
        int in = b2buf[(k - 1) % 3], o = b2buf[k % 3], pv = b2buf[(k - 2) % 3];
        k_step2<<<N2 / 8, 256>>>(in, o, pv, 1, W2, k, (k < KCH - 1) ? 1 : 0);
    }

    // --- fc + log_softmax ---
    k_fc<<<192, 256>>>(fcw);
    k_lsm<<<1, 32>>>(fcb, out);
}